// round 14
// baseline (speedup 1.0000x reference)
#include <cuda_runtime.h>
#include <math.h>

#define BB 32
#define CC 64
#define LL 4096
#define NHALF 2048
#define PADI(i) ((i) + ((i) >> 5))
typedef unsigned long long ull;

// ---------------- f32x2 helpers ----------------
__device__ __forceinline__ ull pk(float lo, float hi) {
    ull r; asm("mov.b64 %0, {%1, %2};" : "=l"(r) : "f"(lo), "f"(hi)); return r;
}
__device__ __forceinline__ void upk(float& lo, float& hi, ull v) {
    asm("mov.b64 {%0, %1}, %2;" : "=f"(lo), "=f"(hi) : "l"(v));
}
__device__ __forceinline__ void fma2(ull& a, ull b, ull c) {
    asm("fma.rn.f32x2 %0, %1, %2, %0;" : "+l"(a) : "l"(b), "l"(c));
}

// ---------------- scratch ----------------
static __device__ float  g_percol[BB * CC * 4];   // sumx, max|d1|, max|d2|, zc
static __device__ float  g_specp[BB * CC * 3];    // per-(b,c) tot, cen, hi
static __device__ float  g_weights[BB * 4];
static __device__ float  g_svm[BB * LL];
static __device__ double g_pd[BB * 4 * 4];        // per (b,quarter): s, sq, s2, sq2
static __device__ float  g_pf[BB * 4 * 4];        // pre, post, mx, midmx
static __device__ float  g_gnp[BB * CC * 2];      // per-(b,c) sum, sumsq of mixed
static __device__ float  g_mixed[(size_t)BB * CC * LL];

// ---------------- block reductions ----------------
__device__ __forceinline__ float bsumf(float v) {
    __shared__ float sh[32];
    int lane = threadIdx.x & 31, w = threadIdx.x >> 5;
#pragma unroll
    for (int o = 16; o; o >>= 1) v += __shfl_down_sync(0xffffffffu, v, o);
    __syncthreads();
    if (lane == 0) sh[w] = v;
    __syncthreads();
    if (w == 0) {
        int nw = (blockDim.x + 31) >> 5;
        float t = (lane < nw) ? sh[lane] : 0.f;
#pragma unroll
        for (int o = 16; o; o >>= 1) t += __shfl_down_sync(0xffffffffu, t, o);
        if (lane == 0) sh[0] = t;
    }
    __syncthreads();
    return sh[0];
}

__device__ __forceinline__ double bsumd(double v) {
    __shared__ double shd[32];
    int lane = threadIdx.x & 31, w = threadIdx.x >> 5;
#pragma unroll
    for (int o = 16; o; o >>= 1) v += __shfl_down_sync(0xffffffffu, v, o);
    __syncthreads();
    if (lane == 0) shd[w] = v;
    __syncthreads();
    if (w == 0) {
        int nw = (blockDim.x + 31) >> 5;
        double t = (lane < nw) ? shd[lane] : 0.0;
#pragma unroll
        for (int o = 16; o; o >>= 1) t += __shfl_down_sync(0xffffffffu, t, o);
        if (lane == 0) shd[0] = t;
    }
    __syncthreads();
    return shd[0];
}

__device__ __forceinline__ float bmaxf(float v) {
    __shared__ float shm[32];
    int lane = threadIdx.x & 31, w = threadIdx.x >> 5;
#pragma unroll
    for (int o = 16; o; o >>= 1) v = fmaxf(v, __shfl_down_sync(0xffffffffu, v, o));
    __syncthreads();
    if (lane == 0) shm[w] = v;
    __syncthreads();
    if (w == 0) {
        int nw = (blockDim.x + 31) >> 5;
        float t = (lane < nw) ? shm[lane] : -INFINITY;
#pragma unroll
        for (int o = 16; o; o >>= 1) t = fmaxf(t, __shfl_down_sync(0xffffffffu, t, o));
        if (lane == 0) shm[0] = t;
    }
    __syncthreads();
    return shm[0];
}

// ---------------- FFT butterflies ----------------
__device__ __forceinline__ void bf(float2& u, float2& v, float2 w) {
    float ux = u.x, uy = u.y;
    u.x = ux + v.x; u.y = uy + v.y;
    float dx = ux - v.x, dy = uy - v.y;
    v.x = dx * w.x - dy * w.y;
    v.y = dx * w.y + dy * w.x;
}
__device__ __forceinline__ void bf1(float2& u, float2& v) {
    float ux = u.x, uy = u.y;
    u.x = ux + v.x; u.y = uy + v.y;
    v.x = ux - v.x; v.y = uy - v.y;
}
__device__ __forceinline__ void bfmi(float2& u, float2& v) {
    float ux = u.x, uy = u.y;
    u.x = ux + v.x; u.y = uy + v.y;
    float dx = ux - v.x, dy = uy - v.y;
    v.x = dy; v.y = -dx;
}

// ---------------- fat kernel: blocks [0,2048) = FFT+percol, [2048,2176) = svm ----------------
__global__ void __launch_bounds__(256) k_fat(const float* __restrict__ x) {
    __shared__ float2 Z[PADI(2047) + 1 + 8];
    __shared__ float2 TW[1025];
    int t = threadIdx.x;

    if (blockIdx.x < BB * CC) {
        // ======================= FFT branch =======================
        int bc = blockIdx.x;
        const float* xr = x + (size_t)bc * LL;

        for (int e = t; e < 1025; e += 256) {
            float sn, cs;
            __sincosf(-3.14159265358979f * (float)e / 1024.f, &sn, &cs);
            TW[e] = make_float2(cs, sn);
        }

        float2 r[8];
        float psum = 0.f, m1 = 0.f, m2 = 0.f, zc = 0.f;
#pragma unroll
        for (int j = 0; j < 8; j++) {
            int idx = t + 256 * j;
            float x0 = xr[2 * idx], x1 = xr[2 * idx + 1];
            r[j] = make_float2(x0, x1);
            psum += x0 + x1;
            m1 = fmaxf(m1, fabsf(x1 - x0));
            if (x0 * x1 < 0.f) zc += 1.f;
            if (idx < 2047) {
                float x2 = xr[2 * idx + 2], x3 = xr[2 * idx + 3];
                m1 = fmaxf(m1, fabsf(x2 - x1));
                if (x1 * x2 < 0.f) zc += 1.f;
                m2 = fmaxf(m2, fabsf(x2 - 2.f * x1 + x0));
                m2 = fmaxf(m2, fabsf(x3 - 2.f * x2 + x1));
            }
        }
        psum = bsumf(psum); zc = bsumf(zc);
        m1 = bmaxf(m1); m2 = bmaxf(m2);
        if (t == 0) {
            float* p = g_percol + bc * 4;
            p[0] = psum; p[1] = m1; p[2] = m2; p[3] = zc;
        }
        __syncthreads();

        // group 1: h = 1024, 512, 256
#pragma unroll
        for (int j = 0; j < 4; j++) bf(r[j], r[j + 4], TW[t + 256 * j]);
        bf(r[0], r[2], TW[2 * t]);   bf(r[1], r[3], TW[2 * t + 512]);
        bf(r[4], r[6], TW[2 * t]);   bf(r[5], r[7], TW[2 * t + 512]);
        bf(r[0], r[1], TW[4 * t]);   bf(r[2], r[3], TW[4 * t]);
        bf(r[4], r[5], TW[4 * t]);   bf(r[6], r[7], TW[4 * t]);
#pragma unroll
        for (int j = 0; j < 8; j++) Z[PADI(t + 256 * j)] = r[j];
        __syncthreads();

        // group 2: h = 128, 64, 32
        {
            int g = t >> 5, u = t & 31;
            int base = g * 256 + u;
#pragma unroll
            for (int j = 0; j < 8; j++) r[j] = Z[PADI(base + 32 * j)];
#pragma unroll
            for (int j = 0; j < 4; j++) bf(r[j], r[j + 4], TW[8 * (u + 32 * j)]);
            bf(r[0], r[2], TW[16 * u]);      bf(r[1], r[3], TW[16 * (u + 32)]);
            bf(r[4], r[6], TW[16 * u]);      bf(r[5], r[7], TW[16 * (u + 32)]);
            bf(r[0], r[1], TW[32 * u]);      bf(r[2], r[3], TW[32 * u]);
            bf(r[4], r[5], TW[32 * u]);      bf(r[6], r[7], TW[32 * u]);
#pragma unroll
            for (int j = 0; j < 8; j++) Z[PADI(base + 32 * j)] = r[j];
        }
        __syncthreads();

        // group 3: h = 16, 8, 4
        {
            int q = t >> 2, v = t & 3;
            int base = q * 32 + v;
#pragma unroll
            for (int j = 0; j < 8; j++) r[j] = Z[PADI(base + 4 * j)];
#pragma unroll
            for (int j = 0; j < 4; j++) bf(r[j], r[j + 4], TW[64 * (v + 4 * j)]);
            bf(r[0], r[2], TW[128 * v]);     bf(r[1], r[3], TW[128 * (v + 4)]);
            bf(r[4], r[6], TW[128 * v]);     bf(r[5], r[7], TW[128 * (v + 4)]);
            bf(r[0], r[1], TW[256 * v]);     bf(r[2], r[3], TW[256 * v]);
            bf(r[4], r[5], TW[256 * v]);     bf(r[6], r[7], TW[256 * v]);
#pragma unroll
            for (int j = 0; j < 8; j++) Z[PADI(base + 4 * j)] = r[j];
        }
        __syncthreads();

        // group 4: h = 2, 1; scatter to natural order
        {
#pragma unroll
            for (int j = 0; j < 8; j++) r[j] = Z[PADI(8 * t + j)];
            bf1(r[0], r[2]); bfmi(r[1], r[3]);
            bf1(r[4], r[6]); bfmi(r[5], r[7]);
            bf1(r[0], r[1]); bf1(r[2], r[3]);
            bf1(r[4], r[5]); bf1(r[6], r[7]);
            int rev8t = (int)(__brev((unsigned)t) >> 24);
            const int rev3[8] = {0, 4, 2, 6, 1, 5, 3, 7};
            __syncthreads();
#pragma unroll
            for (int j = 0; j < 8; j++)
                Z[PADI((rev3[j] << 8) | rev8t)] = r[j];
        }
        __syncthreads();

        // unpack real bins via TW table (even k: TW[k/2]; odd k: TW[k/2] * rot)
        float rsn, rc;
        __sincosf(-3.14159265358979f / 2048.f, &rsn, &rc);
        float tot = 0.f, cen = 0.f, hi = 0.f;
        for (int k = t; k <= NHALF; k += 256) {
            int ik = k & (NHALF - 1);
            int im = (NHALF - k) & (NHALF - 1);
            float2 Zk = Z[PADI(ik)], Zm = Z[PADI(im)];
            float zex = 0.5f * (Zk.x + Zm.x), zey = 0.5f * (Zk.y - Zm.y);
            float zox = 0.5f * (Zk.y + Zm.y), zoy = -0.5f * (Zk.x - Zm.x);
            float2 w = TW[k >> 1];
            float rcc = (k & 1) ? rc : 1.f;
            float rss = (k & 1) ? rsn : 0.f;
            float wx = w.x * rcc - w.y * rss;
            float wy = w.x * rss + w.y * rcc;
            float Xr = zex + wx * zox - wy * zoy;
            float Xi = zey + wx * zoy + wy * zox;
            float p = (Xr * Xr + Xi * Xi) * (1.f / 4096.f);
            tot += p;
            cen += p * ((float)k * (1.f / 2048.f));
            if (k >= 820) hi += p;
        }
        tot = bsumf(tot); cen = bsumf(cen); hi = bsumf(hi);
        if (t == 0) {
            float* sp = g_specp + bc * 3;
            sp[0] = tot; sp[1] = cen; sp[2] = hi;
        }
    } else {
        // ======================= svm branch =======================
        int idx = blockIdx.x - BB * CC;
        int b = idx >> 2, quarter = idx & 3;
        int l0 = quarter * 1024 + t * 4;
        const float* xb = x + (size_t)b * CC * LL;

        ull a01 = pk(0.f, 0.f), a23 = a01;
#pragma unroll
        for (int c = 0; c < CC; c++) {
            ulonglong2 v2 = *reinterpret_cast<const ulonglong2*>(xb + (size_t)c * LL + l0);
            fma2(a01, v2.x, v2.x);
            fma2(a23, v2.y, v2.y);
        }
        float q0, q1, q2, q3;
        upk(q0, q1, a01); upk(q2, q3, a23);
        float sv[4] = {sqrtf(q0), sqrtf(q1), sqrtf(q2), sqrtf(q3)};
        *reinterpret_cast<float4*>(g_svm + b * LL + l0) =
            make_float4(sv[0], sv[1], sv[2], sv[3]);

        double s = 0, sq = 0, s2 = 0, sq2 = 0;
        float pre = 0.f, post = 0.f, mx = 0.f, mid = 0.f;
#pragma unroll
        for (int k = 0; k < 4; k++) {
            int l = l0 + k;
            float v = sv[k];
            s += v; sq += (double)v * v;
            if (l >= 2048) { s2 += v; sq2 += (double)v * v; }
            if (l < 1365)      pre += v;
            else if (l < 2730) mid = fmaxf(mid, v);
            else               post += v;
            mx = fmaxf(mx, v);
        }
        s = bsumd(s); sq = bsumd(sq); s2 = bsumd(s2); sq2 = bsumd(sq2);
        pre = bsumf(pre); post = bsumf(post);
        mx = bmaxf(mx); mid = bmaxf(mid);
        if (t == 0) {
            double* pd = g_pd + idx * 4;
            pd[0] = s; pd[1] = sq; pd[2] = s2; pd[3] = sq2;
            float* pf = g_pf + idx * 4;
            pf[0] = pre; pf[1] = post; pf[2] = mx; pf[3] = mid;
        }
    }
}

// ---------------- gate: svm finalize + counts + MLPs -> weights ----------------
__global__ void __launch_bounds__(256) k_gate(
        const float* __restrict__ comp_w1, const float* __restrict__ comp_b1,
        const float* __restrict__ comp_w2, const float* __restrict__ comp_b2,
        const float* __restrict__ pn_g, const float* __restrict__ pn_b,
        const float* __restrict__ pn_m, const float* __restrict__ pn_v,
        const float* __restrict__ pe_w1, const float* __restrict__ pe_b1,
        const float* __restrict__ pe_w2, const float* __restrict__ pe_b2,
        const float* __restrict__ pg_w, const float* __restrict__ pg_b,
        const float* __restrict__ temperature) {
    int b = blockIdx.x, t = threadIdx.x;
    __shared__ float xm[CC], h[CC], p1[32], p2[32], pf[12], zz[4];
    __shared__ float sthr[3], sf[4];

    if (t == 0) {
        double s = 0, sq = 0, s2 = 0, sq2 = 0;
        float pre = 0, post = 0, mx = 0, mid = 0;
        for (int q = 0; q < 4; q++) {
            const double* pd = g_pd + (b * 4 + q) * 4;
            s += pd[0]; sq += pd[1]; s2 += pd[2]; sq2 += pd[3];
            const float* pp = g_pf + (b * 4 + q) * 4;
            pre += pp[0]; post += pp[1];
            mx = fmaxf(mx, pp[2]); mid = fmaxf(mid, pp[3]);
        }
        float mean = (float)(s / LL);
        float var1 = (float)((sq - s * s / LL) / (LL - 1));
        float sdev = sqrtf(fmaxf(var1, 0.f)) + 1e-6f;
        sthr[0] = mean + 2.f * sdev;
        sthr[1] = mean + 3.f * sdev;
        sthr[2] = mean - sdev;
        sf[0] = mx; sf[1] = mean;
        double var2 = (sq2 - s2 * s2 / NHALF) / (NHALF - 1);
        float std2 = sqrtf(fmaxf((float)var2, 0.f));
        sf[2] = tanhf(1.f / (std2 + 1e-6f));
        float prem = pre / 1365.f, postm = post / 1366.f;
        float fp = fmaxf(mid - prem, 0.f) + fmaxf(mid - postm, 0.f);
        sf[3] = fp / (fabsf(mid) + 1e-6f);
    }
    __syncthreads();

    float thr = sthr[0], hthr = sthr[1], lthr = sthr[2];
    float c1 = 0.f, c2 = 0.f, c3 = 0.f;
    const float* sr = g_svm + b * LL;
    for (int l = t; l < LL; l += 256) {
        float sv = sr[l];
        if (sv > thr)  c1 += 1.f;
        if (sv > hthr) c2 += 1.f;
        if (sv < lthr) c3 += 1.f;
    }
    c1 = bsumf(c1); c2 = bsumf(c2); c3 = bsumf(c3);

    float tpv = 0, cnv = 0, hiv = 0, jmv = 0, jrv = 0, zcv = 0;
    if (t < 64) {
        const float* sp = g_specp + (b * 64 + t) * 3;
        tpv = sp[0]; cnv = sp[1]; hiv = sp[2];
        const float* pc = g_percol + (b * 64 + t) * 4;
        xm[t] = pc[0] * (1.f / LL);
        jmv = pc[1]; jrv = pc[2]; zcv = pc[3];
    }
    float tp = bsumf(tpv), cn = bsumf(cnv), hh = bsumf(hiv);
    float jm = bsumf(jmv), jr = bsumf(jrv), zc = bsumf(zcv);

    if (t == 0) {
        float f[12];
        f[0] = sf[0]; f[1] = sf[1]; f[7] = sf[2]; f[11] = sf[3];
        f[2] = jm * (1.f / CC) * 50.f;
        f[3] = jr * (1.f / CC) * 2500.f;
        f[4] = zc * (1.f / CC) * (1.f / LL);
        f[5] = c1 / LL; f[6] = c2 / LL; f[8] = c3 / LL;
        f[9] = cn / (tp + 1e-6f);
        f[10] = hh / (tp + 1e-6f);
        for (int i = 0; i < 12; i++) {
            float v = f[i];
            if (!isfinite(v)) v = 0.f;
            pf[i] = (v - pn_m[i]) * rsqrtf(pn_v[i] + 1e-5f) * pn_g[i] + pn_b[i];
        }
    }
    __syncthreads();

    if (t < 64) {
        float acc = comp_b1[t];
        for (int c = 0; c < CC; c++) acc = fmaf(xm[c], comp_w1[c * CC + t], acc);
        h[t] = fmaxf(acc, 0.f);
        if (t < 32) {
            float q1 = pe_b1[t];
            for (int i = 0; i < 12; i++) q1 = fmaf(pf[i], pe_w1[i * 32 + t], q1);
            p1[t] = fmaxf(q1, 0.f);
        }
    }
    __syncthreads();
    if (t < 32) {
        float q2 = pe_b2[t];
        for (int i = 0; i < 32; i++) q2 = fmaf(p1[i], pe_w2[i * 32 + t], q2);
        p2[t] = fmaxf(q2, 0.f);
    }
    __syncthreads();
    if (t < 4) {
        float lg = comp_b2[t];
        for (int i = 0; i < CC; i++) lg = fmaf(h[i], comp_w2[i * 4 + t], lg);
        float pg = pg_b[t];
        for (int i = 0; i < 32; i++) pg = fmaf(p2[i], pg_w[i * 4 + t], pg);
        float pw = 1.f / (1.f + expf(-pg));
        float temp = fmaxf(temperature[0], 0.1f);
        zz[t] = lg * pw / temp;
    }
    __syncthreads();
    if (t == 0) {
        float m = fmaxf(fmaxf(zz[0], zz[1]), fmaxf(zz[2], zz[3]));
        float e0 = expf(zz[0] - m), e1 = expf(zz[1] - m);
        float e2 = expf(zz[2] - m), e3 = expf(zz[3] - m);
        float si = 1.f / (e0 + e1 + e2 + e3);
        g_weights[b * 4 + 0] = e0 * si;
        g_weights[b * 4 + 1] = e1 * si;
        g_weights[b * 4 + 2] = e2 * si;
        g_weights[b * 4 + 3] = e3 * si;
    }
}

// ---------------- combined 63-tap conv with f32x2 dual-parity window ----------------
#define XS_LEN (LL + 62 + 8)
__global__ void __launch_bounds__(256) k_conv(
        const float* __restrict__ x,
        const float* __restrict__ w7, const float* __restrict__ w15,
        const float* __restrict__ w31, const float* __restrict__ w63,
        const float* __restrict__ bn_g, const float* __restrict__ bn_b,
        const float* __restrict__ bn_m, const float* __restrict__ bn_v) {
    int bc = blockIdx.x;
    int b = bc >> 6, c = bc & 63;
    __shared__ __align__(16) float coef[64];
    __shared__ float sbias;
    __shared__ __align__(16) float xs[XS_LEN];
    int t = threadIdx.x;

    float wk0 = g_weights[b * 4 + 0], wk1 = g_weights[b * 4 + 1];
    float wk2 = g_weights[b * 4 + 2], wk3 = g_weights[b * 4 + 3];
    if (t < 64) {
        float sc0 = bn_g[0 * CC + c] * rsqrtf(bn_v[0 * CC + c] + 1e-5f);
        float sc1 = bn_g[1 * CC + c] * rsqrtf(bn_v[1 * CC + c] + 1e-5f);
        float sc2 = bn_g[2 * CC + c] * rsqrtf(bn_v[2 * CC + c] + 1e-5f);
        float sc3 = bn_g[3 * CC + c] * rsqrtf(bn_v[3 * CC + c] + 1e-5f);
        if (t < 63) {
            int o = t - 31;
            float cf = wk3 * sc3 * w63[c * 63 + t];
            if (o >= -15 && o <= 15) cf += wk2 * sc2 * w31[c * 31 + o + 15];
            if (o >= -7  && o <= 7 ) cf += wk1 * sc1 * w15[c * 15 + o + 7];
            if (o >= -3  && o <= 3 ) cf += wk0 * sc0 * w7 [c * 7  + o + 3];
            coef[t] = cf;
        } else {
            coef[63] = 0.f;
            sbias = wk0 * (bn_b[0 * CC + c] - bn_m[0 * CC + c] * sc0)
                  + wk1 * (bn_b[1 * CC + c] - bn_m[1 * CC + c] * sc1)
                  + wk2 * (bn_b[2 * CC + c] - bn_m[2 * CC + c] * sc2)
                  + wk3 * (bn_b[3 * CC + c] - bn_m[3 * CC + c] * sc3);
        }
    }
    const float* xr = x + (size_t)bc * LL;
    for (int i = t; i < XS_LEN; i += 256) {
        int l = i - 31;
        xs[i] = (l >= 0 && l < LL) ? xr[l] : 0.f;
    }
    __syncthreads();

    int o0 = t * 16;
    float bias = sbias;
    ull acc2[8];
    ull bias2 = pk(bias, bias);
#pragma unroll
    for (int m = 0; m < 8; m++) acc2[m] = bias2;

    const float4* xs4 = reinterpret_cast<const float4*>(xs + o0);
    const float4* cf4 = reinterpret_cast<const float4*>(coef);

    ull pE[10], pO[9];
    float last;
    {
        float v[20];
#pragma unroll
        for (int q = 0; q < 5; q++) {
            float4 t4 = xs4[q];
            v[4 * q + 0] = t4.x; v[4 * q + 1] = t4.y;
            v[4 * q + 2] = t4.z; v[4 * q + 3] = t4.w;
        }
#pragma unroll
        for (int k = 0; k < 10; k++) pE[k] = pk(v[2 * k], v[2 * k + 1]);
#pragma unroll
        for (int k = 0; k < 9; k++)  pO[k] = pk(v[2 * k + 1], v[2 * k + 2]);
        last = v[19];
    }

#pragma unroll
    for (int g = 0; g < 16; g++) {
        float4 cv = cf4[g];
        ull c0 = pk(cv.x, cv.x), c1 = pk(cv.y, cv.y);
        ull c2 = pk(cv.z, cv.z), c3 = pk(cv.w, cv.w);
#pragma unroll
        for (int m = 0; m < 8; m++) fma2(acc2[m], c0, pE[m]);
#pragma unroll
        for (int m = 0; m < 8; m++) fma2(acc2[m], c1, pO[m]);
#pragma unroll
        for (int m = 0; m < 8; m++) fma2(acc2[m], c2, pE[m + 1]);
#pragma unroll
        for (int m = 0; m < 8; m++) fma2(acc2[m], c3, pO[m + 1]);
        if (g < 15) {
            float4 nv = xs4[5 + g];
#pragma unroll
            for (int m = 0; m < 8; m++) pE[m] = pE[m + 2];
#pragma unroll
            for (int m = 0; m < 7; m++) pO[m] = pO[m + 2];
            pE[8] = pk(nv.x, nv.y); pE[9] = pk(nv.z, nv.w);
            pO[7] = pk(last, nv.x); pO[8] = pk(nv.y, nv.z);
            last = nv.w;
        }
    }

    float outv[16];
#pragma unroll
    for (int m = 0; m < 8; m++) upk(outv[2 * m], outv[2 * m + 1], acc2[m]);

    float ls = 0.f, lsq = 0.f;
    float* mrow = g_mixed + (size_t)bc * LL + o0;
#pragma unroll
    for (int j = 0; j < 16; j += 4) {
        *reinterpret_cast<float4*>(mrow + j) =
            make_float4(outv[j], outv[j + 1], outv[j + 2], outv[j + 3]);
#pragma unroll
        for (int k = 0; k < 4; k++) {
            float v = outv[j + k];
            ls += v; lsq += v * v;
        }
    }
    ls = bsumf(ls); lsq = bsumf(lsq);
    if (t == 0) {
        g_gnp[bc * 2 + 0] = ls;
        g_gnp[bc * 2 + 1] = lsq;
    }
}

// ---------------- act: in-place GN + GELU on g_mixed (pure streaming) ----------------
__global__ void __launch_bounds__(256) k_act(
        const float* __restrict__ gn_g, const float* __restrict__ gn_b) {
    int t = threadIdx.x;
    int b = blockIdx.x >> 5;
    int chunk = blockIdx.x & 31;   // covers 2 c-rows
    int c0 = chunk * 2;

    // GN stats from per-(b,c) partials
    float sval = (t < 64) ? g_gnp[(b * 64 + t) * 2 + 0] : 0.f;
    float qval = (t >= 64 && t < 128) ? g_gnp[(b * 64 + (t - 64)) * 2 + 1] : 0.f;
    float S = bsumf(sval);
    float Q = bsumf(qval);
    float n = (float)(CC * LL);
    float mu = S / n;
    float istd = rsqrtf(Q / n - mu * mu + 1e-5f);

    float* base = g_mixed + ((size_t)b * CC + c0) * LL;
    // 2 rows x 4096 floats = 2048 float4; 8 per thread
#pragma unroll
    for (int i = 0; i < 8; i++) {
        int idx = t + 256 * i;            // 0..2047
        int r = idx >> 10;                // row 0 or 1
        float gg = gn_g[c0 + r], gb = gn_b[c0 + r];
        float4* p = reinterpret_cast<float4*>(base + (size_t)r * LL + (idx & 1023) * 4);
        float4 mv = *p;
        float v;
        v = (mv.x - mu) * istd * gg + gb; mv.x = 0.5f * v * (1.f + erff(v * 0.70710678f));
        v = (mv.y - mu) * istd * gg + gb; mv.y = 0.5f * v * (1.f + erff(v * 0.70710678f));
        v = (mv.z - mu) * istd * gg + gb; mv.z = 0.5f * v * (1.f + erff(v * 0.70710678f));
        v = (mv.w - mu) * istd * gg + gb; mv.w = 0.5f * v * (1.f + erff(v * 0.70710678f));
        *p = mv;
    }
}

// ---------------- 64x64 projection + residual (stage = plain copy of act) ----------------
#define PROJ_SMEM (64 * 256 * 4 + 64 * 64 * 4)
__global__ void __launch_bounds__(256) k_proj(
        const float* __restrict__ x,
        const float* __restrict__ proj_w, const float* __restrict__ proj_b,
        const float* __restrict__ res_scale, float* __restrict__ out) {
    extern __shared__ __align__(16) float sm[];
    float* As = sm;             // [64][256]
    float* Ws = sm + 64 * 256;  // [c][o] transposed
    int t = threadIdx.x;
    int b = blockIdx.x >> 4;
    int l0 = (blockIdx.x & 15) * 256;

    // stage A (already activated) + W transpose
    for (int idx = t; idx < 4096; idx += 256) {
        int c = idx >> 6, j = idx & 63;
        float4 mv = *reinterpret_cast<const float4*>(
            g_mixed + (size_t)(b * 64 + c) * LL + l0 + j * 4);
        *reinterpret_cast<float4*>(As + c * 256 + j * 4) = mv;
    }
    for (int idx = t; idx < 4096; idx += 256) {
        int c = idx >> 6, o = idx & 63;
        Ws[c * 64 + o] = proj_w[o * CC + c];
    }
    __syncthreads();

    int to = t >> 4, tl = t & 15;  // 4 outputs (o=to*4..), 16 l (4 quartets at 64q+tl*4)
    ull acc2[4][8];
    ull z2 = pk(0.f, 0.f);
#pragma unroll
    for (int i = 0; i < 4; i++)
#pragma unroll
        for (int p = 0; p < 8; p++) acc2[i][p] = z2;

#pragma unroll 4
    for (int c = 0; c < 64; c++) {
        float4 wv = *reinterpret_cast<const float4*>(Ws + c * 64 + to * 4);
        ull w0 = pk(wv.x, wv.x), w1 = pk(wv.y, wv.y);
        ull w2 = pk(wv.z, wv.z), w3 = pk(wv.w, wv.w);
#pragma unroll
        for (int q = 0; q < 4; q++) {
            ulonglong2 aq = *reinterpret_cast<const ulonglong2*>(
                As + c * 256 + q * 64 + tl * 4);
            fma2(acc2[0][2 * q], w0, aq.x); fma2(acc2[0][2 * q + 1], w0, aq.y);
            fma2(acc2[1][2 * q], w1, aq.x); fma2(acc2[1][2 * q + 1], w1, aq.y);
            fma2(acc2[2][2 * q], w2, aq.x); fma2(acc2[2][2 * q + 1], w2, aq.y);
            fma2(acc2[3][2 * q], w3, aq.x); fma2(acc2[3][2 * q + 1], w3, aq.y);
        }
    }

    float rs = res_scale[0];
#pragma unroll
    for (int i = 0; i < 4; i++) {
        int o = to * 4 + i;
        float pb = proj_b[o];
#pragma unroll
        for (int q = 0; q < 4; q++) {
            float f0, f1, f2, f3;
            upk(f0, f1, acc2[i][2 * q]);
            upk(f2, f3, acc2[i][2 * q + 1]);
            size_t base = ((size_t)(b * 64 + o)) * LL + l0 + q * 64 + tl * 4;
            float4 xv = *reinterpret_cast<const float4*>(x + base);
            float4 ov;
            ov.x = xv.x + rs * (f0 + pb);
            ov.y = xv.y + rs * (f1 + pb);
            ov.z = xv.z + rs * (f2 + pb);
            ov.w = xv.w + rs * (f3 + pb);
            *reinterpret_cast<float4*>(out + base) = ov;
        }
    }
}

// ---------------- launch ----------------
extern "C" void kernel_launch(void* const* d_in, const int* in_sizes, int n_in,
                              void* d_out, int out_size) {
    const float* x       = (const float*)d_in[0];
    const float* dw_w7   = (const float*)d_in[1];
    const float* dw_w15  = (const float*)d_in[2];
    const float* dw_w31  = (const float*)d_in[3];
    const float* dw_w63  = (const float*)d_in[4];
    const float* bn_g    = (const float*)d_in[5];
    const float* bn_b    = (const float*)d_in[6];
    const float* bn_m    = (const float*)d_in[7];
    const float* bn_v    = (const float*)d_in[8];
    const float* comp_w1 = (const float*)d_in[9];
    const float* comp_b1 = (const float*)d_in[10];
    const float* comp_w2 = (const float*)d_in[11];
    const float* comp_b2 = (const float*)d_in[12];
    const float* pn_g    = (const float*)d_in[13];
    const float* pn_b    = (const float*)d_in[14];
    const float* pn_m    = (const float*)d_in[15];
    const float* pn_v    = (const float*)d_in[16];
    const float* pe_w1   = (const float*)d_in[17];
    const float* pe_b1   = (const float*)d_in[18];
    const float* pe_w2   = (const float*)d_in[19];
    const float* pe_b2   = (const float*)d_in[20];
    const float* pg_w    = (const float*)d_in[21];
    const float* pg_b    = (const float*)d_in[22];
    const float* temp    = (const float*)d_in[23];
    const float* gn_g    = (const float*)d_in[24];
    const float* gn_b    = (const float*)d_in[25];
    const float* proj_w  = (const float*)d_in[26];
    const float* proj_b  = (const float*)d_in[27];
    const float* rscale  = (const float*)d_in[28];
    float* out = (float*)d_out;

    cudaFuncSetAttribute(k_proj, cudaFuncAttributeMaxDynamicSharedMemorySize, PROJ_SMEM);

    k_fat<<<BB * CC + BB * 4, 256>>>(x);
    k_gate<<<BB, 256>>>(comp_w1, comp_b1, comp_w2, comp_b2,
                        pn_g, pn_b, pn_m, pn_v,
                        pe_w1, pe_b1, pe_w2, pe_b2, pg_w, pg_b, temp);
    k_conv<<<BB * CC, 256>>>(x, dw_w7, dw_w15, dw_w31, dw_w63,
                             bn_g, bn_b, bn_m, bn_v);
    k_act<<<BB * 32, 256>>>(gn_g, gn_b);
    k_proj<<<BB * 16, 256, PROJ_SMEM>>>(x, proj_w, proj_b, rscale, out);
}

// round 15
// speedup vs baseline: 1.0853x; 1.0853x over previous
#include <cuda_runtime.h>
#include <math.h>

#define BB 32
#define CC 64
#define LL 4096
#define NHALF 2048
#define PADI(i) ((i) + ((i) >> 5))
typedef unsigned long long ull;

// ---------------- f32x2 helpers ----------------
__device__ __forceinline__ ull pk(float lo, float hi) {
    ull r; asm("mov.b64 %0, {%1, %2};" : "=l"(r) : "f"(lo), "f"(hi)); return r;
}
__device__ __forceinline__ void upk(float& lo, float& hi, ull v) {
    asm("mov.b64 {%0, %1}, %2;" : "=f"(lo), "=f"(hi) : "l"(v));
}
__device__ __forceinline__ void fma2(ull& a, ull b, ull c) {
    asm("fma.rn.f32x2 %0, %1, %2, %0;" : "+l"(a) : "l"(b), "l"(c));
}

// ---------------- scratch ----------------
static __device__ float  g_percol[BB * CC * 4];   // sumx, max|d1|, max|d2|, zc
static __device__ float  g_specp[BB * CC * 3];    // per-(b,c) tot, cen, hi
static __device__ float  g_weights[BB * 4];
static __device__ float  g_svm[BB * LL];
static __device__ double g_pd[BB * 4 * 4];        // per (b,quarter): s, sq, s2, sq2
static __device__ float  g_pf[BB * 4 * 4];        // pre, post, mx, midmx
static __device__ float  g_gnp[BB * CC * 2];      // per-(b,c) sum, sumsq of mixed
static __device__ float  g_mixed[(size_t)BB * CC * LL];

// ---------------- block reductions ----------------
__device__ __forceinline__ float bsumf(float v) {
    __shared__ float sh[32];
    int lane = threadIdx.x & 31, w = threadIdx.x >> 5;
#pragma unroll
    for (int o = 16; o; o >>= 1) v += __shfl_down_sync(0xffffffffu, v, o);
    __syncthreads();
    if (lane == 0) sh[w] = v;
    __syncthreads();
    if (w == 0) {
        int nw = (blockDim.x + 31) >> 5;
        float t = (lane < nw) ? sh[lane] : 0.f;
#pragma unroll
        for (int o = 16; o; o >>= 1) t += __shfl_down_sync(0xffffffffu, t, o);
        if (lane == 0) sh[0] = t;
    }
    __syncthreads();
    return sh[0];
}

__device__ __forceinline__ double bsumd(double v) {
    __shared__ double shd[32];
    int lane = threadIdx.x & 31, w = threadIdx.x >> 5;
#pragma unroll
    for (int o = 16; o; o >>= 1) v += __shfl_down_sync(0xffffffffu, v, o);
    __syncthreads();
    if (lane == 0) shd[w] = v;
    __syncthreads();
    if (w == 0) {
        int nw = (blockDim.x + 31) >> 5;
        double t = (lane < nw) ? shd[lane] : 0.0;
#pragma unroll
        for (int o = 16; o; o >>= 1) t += __shfl_down_sync(0xffffffffu, t, o);
        if (lane == 0) shd[0] = t;
    }
    __syncthreads();
    return shd[0];
}

__device__ __forceinline__ float bmaxf(float v) {
    __shared__ float shm[32];
    int lane = threadIdx.x & 31, w = threadIdx.x >> 5;
#pragma unroll
    for (int o = 16; o; o >>= 1) v = fmaxf(v, __shfl_down_sync(0xffffffffu, v, o));
    __syncthreads();
    if (lane == 0) shm[w] = v;
    __syncthreads();
    if (w == 0) {
        int nw = (blockDim.x + 31) >> 5;
        float t = (lane < nw) ? shm[lane] : -INFINITY;
#pragma unroll
        for (int o = 16; o; o >>= 1) t = fmaxf(t, __shfl_down_sync(0xffffffffu, t, o));
        if (lane == 0) shm[0] = t;
    }
    __syncthreads();
    return shm[0];
}

// ---------------- FFT butterflies ----------------
__device__ __forceinline__ void bf(float2& u, float2& v, float2 w) {
    float ux = u.x, uy = u.y;
    u.x = ux + v.x; u.y = uy + v.y;
    float dx = ux - v.x, dy = uy - v.y;
    v.x = dx * w.x - dy * w.y;
    v.y = dx * w.y + dy * w.x;
}
__device__ __forceinline__ void bf1(float2& u, float2& v) {
    float ux = u.x, uy = u.y;
    u.x = ux + v.x; u.y = uy + v.y;
    v.x = ux - v.x; v.y = uy - v.y;
}
__device__ __forceinline__ void bfmi(float2& u, float2& v) {
    float ux = u.x, uy = u.y;
    u.x = ux + v.x; u.y = uy + v.y;
    float dx = ux - v.x, dy = uy - v.y;
    v.x = dy; v.y = -dx;
}

// ---------------- fat kernel: blocks [0,2048) = FFT+percol, [2048,2176) = svm ----------------
__global__ void __launch_bounds__(256) k_fat(const float* __restrict__ x) {
    __shared__ float2 Z[PADI(2047) + 1 + 8];
    __shared__ float2 TW[1025];
    int t = threadIdx.x;

    if (blockIdx.x < BB * CC) {
        // ======================= FFT branch =======================
        int bc = blockIdx.x;
        const float* xr = x + (size_t)bc * LL;

        for (int e = t; e < 1025; e += 256) {
            float sn, cs;
            __sincosf(-3.14159265358979f * (float)e / 1024.f, &sn, &cs);
            TW[e] = make_float2(cs, sn);
        }

        float2 r[8];
        float psum = 0.f, m1 = 0.f, m2 = 0.f, zc = 0.f;
#pragma unroll
        for (int j = 0; j < 8; j++) {
            int idx = t + 256 * j;
            float x0 = xr[2 * idx], x1 = xr[2 * idx + 1];
            r[j] = make_float2(x0, x1);
            psum += x0 + x1;
            m1 = fmaxf(m1, fabsf(x1 - x0));
            if (x0 * x1 < 0.f) zc += 1.f;
            if (idx < 2047) {
                float x2 = xr[2 * idx + 2], x3 = xr[2 * idx + 3];
                m1 = fmaxf(m1, fabsf(x2 - x1));
                if (x1 * x2 < 0.f) zc += 1.f;
                m2 = fmaxf(m2, fabsf(x2 - 2.f * x1 + x0));
                m2 = fmaxf(m2, fabsf(x3 - 2.f * x2 + x1));
            }
        }
        psum = bsumf(psum); zc = bsumf(zc);
        m1 = bmaxf(m1); m2 = bmaxf(m2);
        if (t == 0) {
            float* p = g_percol + bc * 4;
            p[0] = psum; p[1] = m1; p[2] = m2; p[3] = zc;
        }
        __syncthreads();

        // group 1: h = 1024, 512, 256
#pragma unroll
        for (int j = 0; j < 4; j++) bf(r[j], r[j + 4], TW[t + 256 * j]);
        bf(r[0], r[2], TW[2 * t]);   bf(r[1], r[3], TW[2 * t + 512]);
        bf(r[4], r[6], TW[2 * t]);   bf(r[5], r[7], TW[2 * t + 512]);
        bf(r[0], r[1], TW[4 * t]);   bf(r[2], r[3], TW[4 * t]);
        bf(r[4], r[5], TW[4 * t]);   bf(r[6], r[7], TW[4 * t]);
#pragma unroll
        for (int j = 0; j < 8; j++) Z[PADI(t + 256 * j)] = r[j];
        __syncthreads();

        // group 2: h = 128, 64, 32
        {
            int g = t >> 5, u = t & 31;
            int base = g * 256 + u;
#pragma unroll
            for (int j = 0; j < 8; j++) r[j] = Z[PADI(base + 32 * j)];
#pragma unroll
            for (int j = 0; j < 4; j++) bf(r[j], r[j + 4], TW[8 * (u + 32 * j)]);
            bf(r[0], r[2], TW[16 * u]);      bf(r[1], r[3], TW[16 * (u + 32)]);
            bf(r[4], r[6], TW[16 * u]);      bf(r[5], r[7], TW[16 * (u + 32)]);
            bf(r[0], r[1], TW[32 * u]);      bf(r[2], r[3], TW[32 * u]);
            bf(r[4], r[5], TW[32 * u]);      bf(r[6], r[7], TW[32 * u]);
#pragma unroll
            for (int j = 0; j < 8; j++) Z[PADI(base + 32 * j)] = r[j];
        }
        __syncthreads();

        // group 3: h = 16, 8, 4
        {
            int q = t >> 2, v = t & 3;
            int base = q * 32 + v;
#pragma unroll
            for (int j = 0; j < 8; j++) r[j] = Z[PADI(base + 4 * j)];
#pragma unroll
            for (int j = 0; j < 4; j++) bf(r[j], r[j + 4], TW[64 * (v + 4 * j)]);
            bf(r[0], r[2], TW[128 * v]);     bf(r[1], r[3], TW[128 * (v + 4)]);
            bf(r[4], r[6], TW[128 * v]);     bf(r[5], r[7], TW[128 * (v + 4)]);
            bf(r[0], r[1], TW[256 * v]);     bf(r[2], r[3], TW[256 * v]);
            bf(r[4], r[5], TW[256 * v]);     bf(r[6], r[7], TW[256 * v]);
#pragma unroll
            for (int j = 0; j < 8; j++) Z[PADI(base + 4 * j)] = r[j];
        }
        __syncthreads();

        // group 4: h = 2, 1; scatter to natural order
        {
#pragma unroll
            for (int j = 0; j < 8; j++) r[j] = Z[PADI(8 * t + j)];
            bf1(r[0], r[2]); bfmi(r[1], r[3]);
            bf1(r[4], r[6]); bfmi(r[5], r[7]);
            bf1(r[0], r[1]); bf1(r[2], r[3]);
            bf1(r[4], r[5]); bf1(r[6], r[7]);
            int rev8t = (int)(__brev((unsigned)t) >> 24);
            const int rev3[8] = {0, 4, 2, 6, 1, 5, 3, 7};
            __syncthreads();
#pragma unroll
            for (int j = 0; j < 8; j++)
                Z[PADI((rev3[j] << 8) | rev8t)] = r[j];
        }
        __syncthreads();

        // unpack real bins via TW table (even k: TW[k/2]; odd k: TW[k/2] * rot)
        float rsn, rc;
        __sincosf(-3.14159265358979f / 2048.f, &rsn, &rc);
        float tot = 0.f, cen = 0.f, hi = 0.f;
        for (int k = t; k <= NHALF; k += 256) {
            int ik = k & (NHALF - 1);
            int im = (NHALF - k) & (NHALF - 1);
            float2 Zk = Z[PADI(ik)], Zm = Z[PADI(im)];
            float zex = 0.5f * (Zk.x + Zm.x), zey = 0.5f * (Zk.y - Zm.y);
            float zox = 0.5f * (Zk.y + Zm.y), zoy = -0.5f * (Zk.x - Zm.x);
            float2 w = TW[k >> 1];
            float rcc = (k & 1) ? rc : 1.f;
            float rss = (k & 1) ? rsn : 0.f;
            float wx = w.x * rcc - w.y * rss;
            float wy = w.x * rss + w.y * rcc;
            float Xr = zex + wx * zox - wy * zoy;
            float Xi = zey + wx * zoy + wy * zox;
            float p = (Xr * Xr + Xi * Xi) * (1.f / 4096.f);
            tot += p;
            cen += p * ((float)k * (1.f / 2048.f));
            if (k >= 820) hi += p;
        }
        tot = bsumf(tot); cen = bsumf(cen); hi = bsumf(hi);
        if (t == 0) {
            float* sp = g_specp + bc * 3;
            sp[0] = tot; sp[1] = cen; sp[2] = hi;
        }
    } else {
        // ======================= svm branch =======================
        int idx = blockIdx.x - BB * CC;
        int b = idx >> 2, quarter = idx & 3;
        int l0 = quarter * 1024 + t * 4;
        const float* xb = x + (size_t)b * CC * LL;

        ull a01 = pk(0.f, 0.f), a23 = a01;
#pragma unroll
        for (int c = 0; c < CC; c++) {
            ulonglong2 v2 = *reinterpret_cast<const ulonglong2*>(xb + (size_t)c * LL + l0);
            fma2(a01, v2.x, v2.x);
            fma2(a23, v2.y, v2.y);
        }
        float q0, q1, q2, q3;
        upk(q0, q1, a01); upk(q2, q3, a23);
        float sv[4] = {sqrtf(q0), sqrtf(q1), sqrtf(q2), sqrtf(q3)};
        *reinterpret_cast<float4*>(g_svm + b * LL + l0) =
            make_float4(sv[0], sv[1], sv[2], sv[3]);

        double s = 0, sq = 0, s2 = 0, sq2 = 0;
        float pre = 0.f, post = 0.f, mx = 0.f, mid = 0.f;
#pragma unroll
        for (int k = 0; k < 4; k++) {
            int l = l0 + k;
            float v = sv[k];
            s += v; sq += (double)v * v;
            if (l >= 2048) { s2 += v; sq2 += (double)v * v; }
            if (l < 1365)      pre += v;
            else if (l < 2730) mid = fmaxf(mid, v);
            else               post += v;
            mx = fmaxf(mx, v);
        }
        s = bsumd(s); sq = bsumd(sq); s2 = bsumd(s2); sq2 = bsumd(sq2);
        pre = bsumf(pre); post = bsumf(post);
        mx = bmaxf(mx); mid = bmaxf(mid);
        if (t == 0) {
            double* pd = g_pd + idx * 4;
            pd[0] = s; pd[1] = sq; pd[2] = s2; pd[3] = sq2;
            float* pf = g_pf + idx * 4;
            pf[0] = pre; pf[1] = post; pf[2] = mx; pf[3] = mid;
        }
    }
}

// ---------------- gate: svm finalize + counts + MLPs -> weights ----------------
__global__ void __launch_bounds__(256) k_gate(
        const float* __restrict__ comp_w1, const float* __restrict__ comp_b1,
        const float* __restrict__ comp_w2, const float* __restrict__ comp_b2,
        const float* __restrict__ pn_g, const float* __restrict__ pn_b,
        const float* __restrict__ pn_m, const float* __restrict__ pn_v,
        const float* __restrict__ pe_w1, const float* __restrict__ pe_b1,
        const float* __restrict__ pe_w2, const float* __restrict__ pe_b2,
        const float* __restrict__ pg_w, const float* __restrict__ pg_b,
        const float* __restrict__ temperature) {
    int b = blockIdx.x, t = threadIdx.x;
    __shared__ float xm[CC], h[CC], p1[32], p2[32], pf[12], zz[4];
    __shared__ float sthr[3], sf[4];

    if (t == 0) {
        double s = 0, sq = 0, s2 = 0, sq2 = 0;
        float pre = 0, post = 0, mx = 0, mid = 0;
        for (int q = 0; q < 4; q++) {
            const double* pd = g_pd + (b * 4 + q) * 4;
            s += pd[0]; sq += pd[1]; s2 += pd[2]; sq2 += pd[3];
            const float* pp = g_pf + (b * 4 + q) * 4;
            pre += pp[0]; post += pp[1];
            mx = fmaxf(mx, pp[2]); mid = fmaxf(mid, pp[3]);
        }
        float mean = (float)(s / LL);
        float var1 = (float)((sq - s * s / LL) / (LL - 1));
        float sdev = sqrtf(fmaxf(var1, 0.f)) + 1e-6f;
        sthr[0] = mean + 2.f * sdev;
        sthr[1] = mean + 3.f * sdev;
        sthr[2] = mean - sdev;
        sf[0] = mx; sf[1] = mean;
        double var2 = (sq2 - s2 * s2 / NHALF) / (NHALF - 1);
        float std2 = sqrtf(fmaxf((float)var2, 0.f));
        sf[2] = tanhf(1.f / (std2 + 1e-6f));
        float prem = pre / 1365.f, postm = post / 1366.f;
        float fp = fmaxf(mid - prem, 0.f) + fmaxf(mid - postm, 0.f);
        sf[3] = fp / (fabsf(mid) + 1e-6f);
    }
    __syncthreads();

    float thr = sthr[0], hthr = sthr[1], lthr = sthr[2];
    float c1 = 0.f, c2 = 0.f, c3 = 0.f;
    const float* sr = g_svm + b * LL;
    for (int l = t; l < LL; l += 256) {
        float sv = sr[l];
        if (sv > thr)  c1 += 1.f;
        if (sv > hthr) c2 += 1.f;
        if (sv < lthr) c3 += 1.f;
    }
    c1 = bsumf(c1); c2 = bsumf(c2); c3 = bsumf(c3);

    float tpv = 0, cnv = 0, hiv = 0, jmv = 0, jrv = 0, zcv = 0;
    if (t < 64) {
        const float* sp = g_specp + (b * 64 + t) * 3;
        tpv = sp[0]; cnv = sp[1]; hiv = sp[2];
        const float* pc = g_percol + (b * 64 + t) * 4;
        xm[t] = pc[0] * (1.f / LL);
        jmv = pc[1]; jrv = pc[2]; zcv = pc[3];
    }
    float tp = bsumf(tpv), cn = bsumf(cnv), hh = bsumf(hiv);
    float jm = bsumf(jmv), jr = bsumf(jrv), zc = bsumf(zcv);

    if (t == 0) {
        float f[12];
        f[0] = sf[0]; f[1] = sf[1]; f[7] = sf[2]; f[11] = sf[3];
        f[2] = jm * (1.f / CC) * 50.f;
        f[3] = jr * (1.f / CC) * 2500.f;
        f[4] = zc * (1.f / CC) * (1.f / LL);
        f[5] = c1 / LL; f[6] = c2 / LL; f[8] = c3 / LL;
        f[9] = cn / (tp + 1e-6f);
        f[10] = hh / (tp + 1e-6f);
        for (int i = 0; i < 12; i++) {
            float v = f[i];
            if (!isfinite(v)) v = 0.f;
            pf[i] = (v - pn_m[i]) * rsqrtf(pn_v[i] + 1e-5f) * pn_g[i] + pn_b[i];
        }
    }
    __syncthreads();

    if (t < 64) {
        float acc = comp_b1[t];
        for (int c = 0; c < CC; c++) acc = fmaf(xm[c], comp_w1[c * CC + t], acc);
        h[t] = fmaxf(acc, 0.f);
        if (t < 32) {
            float q1 = pe_b1[t];
            for (int i = 0; i < 12; i++) q1 = fmaf(pf[i], pe_w1[i * 32 + t], q1);
            p1[t] = fmaxf(q1, 0.f);
        }
    }
    __syncthreads();
    if (t < 32) {
        float q2 = pe_b2[t];
        for (int i = 0; i < 32; i++) q2 = fmaf(p1[i], pe_w2[i * 32 + t], q2);
        p2[t] = fmaxf(q2, 0.f);
    }
    __syncthreads();
    if (t < 4) {
        float lg = comp_b2[t];
        for (int i = 0; i < CC; i++) lg = fmaf(h[i], comp_w2[i * 4 + t], lg);
        float pg = pg_b[t];
        for (int i = 0; i < 32; i++) pg = fmaf(p2[i], pg_w[i * 4 + t], pg);
        float pw = 1.f / (1.f + expf(-pg));
        float temp = fmaxf(temperature[0], 0.1f);
        zz[t] = lg * pw / temp;
    }
    __syncthreads();
    if (t == 0) {
        float m = fmaxf(fmaxf(zz[0], zz[1]), fmaxf(zz[2], zz[3]));
        float e0 = expf(zz[0] - m), e1 = expf(zz[1] - m);
        float e2 = expf(zz[2] - m), e3 = expf(zz[3] - m);
        float si = 1.f / (e0 + e1 + e2 + e3);
        g_weights[b * 4 + 0] = e0 * si;
        g_weights[b * 4 + 1] = e1 * si;
        g_weights[b * 4 + 2] = e2 * si;
        g_weights[b * 4 + 3] = e3 * si;
    }
}

// ---------------- combined 63-tap conv with f32x2 dual-parity window ----------------
#define XS_LEN (LL + 62 + 8)
__global__ void __launch_bounds__(256) k_conv(
        const float* __restrict__ x,
        const float* __restrict__ w7, const float* __restrict__ w15,
        const float* __restrict__ w31, const float* __restrict__ w63,
        const float* __restrict__ bn_g, const float* __restrict__ bn_b,
        const float* __restrict__ bn_m, const float* __restrict__ bn_v) {
    int bc = blockIdx.x;
    int b = bc >> 6, c = bc & 63;
    __shared__ __align__(16) float coef[64];
    __shared__ float sbias;
    __shared__ __align__(16) float xs[XS_LEN];
    int t = threadIdx.x;

    float wk0 = g_weights[b * 4 + 0], wk1 = g_weights[b * 4 + 1];
    float wk2 = g_weights[b * 4 + 2], wk3 = g_weights[b * 4 + 3];
    if (t < 64) {
        float sc0 = bn_g[0 * CC + c] * rsqrtf(bn_v[0 * CC + c] + 1e-5f);
        float sc1 = bn_g[1 * CC + c] * rsqrtf(bn_v[1 * CC + c] + 1e-5f);
        float sc2 = bn_g[2 * CC + c] * rsqrtf(bn_v[2 * CC + c] + 1e-5f);
        float sc3 = bn_g[3 * CC + c] * rsqrtf(bn_v[3 * CC + c] + 1e-5f);
        if (t < 63) {
            int o = t - 31;
            float cf = wk3 * sc3 * w63[c * 63 + t];
            if (o >= -15 && o <= 15) cf += wk2 * sc2 * w31[c * 31 + o + 15];
            if (o >= -7  && o <= 7 ) cf += wk1 * sc1 * w15[c * 15 + o + 7];
            if (o >= -3  && o <= 3 ) cf += wk0 * sc0 * w7 [c * 7  + o + 3];
            coef[t] = cf;
        } else {
            coef[63] = 0.f;
            sbias = wk0 * (bn_b[0 * CC + c] - bn_m[0 * CC + c] * sc0)
                  + wk1 * (bn_b[1 * CC + c] - bn_m[1 * CC + c] * sc1)
                  + wk2 * (bn_b[2 * CC + c] - bn_m[2 * CC + c] * sc2)
                  + wk3 * (bn_b[3 * CC + c] - bn_m[3 * CC + c] * sc3);
        }
    }
    const float* xr = x + (size_t)bc * LL;
    for (int i = t; i < XS_LEN; i += 256) {
        int l = i - 31;
        xs[i] = (l >= 0 && l < LL) ? xr[l] : 0.f;
    }
    __syncthreads();

    int o0 = t * 16;
    float bias = sbias;
    ull acc2[8];
    ull bias2 = pk(bias, bias);
#pragma unroll
    for (int m = 0; m < 8; m++) acc2[m] = bias2;

    const float4* xs4 = reinterpret_cast<const float4*>(xs + o0);
    const float4* cf4 = reinterpret_cast<const float4*>(coef);

    ull pE[10], pO[9];
    float last;
    {
        float v[20];
#pragma unroll
        for (int q = 0; q < 5; q++) {
            float4 t4 = xs4[q];
            v[4 * q + 0] = t4.x; v[4 * q + 1] = t4.y;
            v[4 * q + 2] = t4.z; v[4 * q + 3] = t4.w;
        }
#pragma unroll
        for (int k = 0; k < 10; k++) pE[k] = pk(v[2 * k], v[2 * k + 1]);
#pragma unroll
        for (int k = 0; k < 9; k++)  pO[k] = pk(v[2 * k + 1], v[2 * k + 2]);
        last = v[19];
    }

#pragma unroll
    for (int g = 0; g < 16; g++) {
        float4 cv = cf4[g];
        ull c0 = pk(cv.x, cv.x), c1 = pk(cv.y, cv.y);
        ull c2 = pk(cv.z, cv.z), c3 = pk(cv.w, cv.w);
#pragma unroll
        for (int m = 0; m < 8; m++) fma2(acc2[m], c0, pE[m]);
#pragma unroll
        for (int m = 0; m < 8; m++) fma2(acc2[m], c1, pO[m]);
#pragma unroll
        for (int m = 0; m < 8; m++) fma2(acc2[m], c2, pE[m + 1]);
#pragma unroll
        for (int m = 0; m < 8; m++) fma2(acc2[m], c3, pO[m + 1]);
        if (g < 15) {
            float4 nv = xs4[5 + g];
#pragma unroll
            for (int m = 0; m < 8; m++) pE[m] = pE[m + 2];
#pragma unroll
            for (int m = 0; m < 7; m++) pO[m] = pO[m + 2];
            pE[8] = pk(nv.x, nv.y); pE[9] = pk(nv.z, nv.w);
            pO[7] = pk(last, nv.x); pO[8] = pk(nv.y, nv.z);
            last = nv.w;
        }
    }

    float outv[16];
#pragma unroll
    for (int m = 0; m < 8; m++) upk(outv[2 * m], outv[2 * m + 1], acc2[m]);

    float ls = 0.f, lsq = 0.f;
    float* mrow = g_mixed + (size_t)bc * LL + o0;
#pragma unroll
    for (int j = 0; j < 16; j += 4) {
        *reinterpret_cast<float4*>(mrow + j) =
            make_float4(outv[j], outv[j + 1], outv[j + 2], outv[j + 3]);
#pragma unroll
        for (int k = 0; k < 4; k++) {
            float v = outv[j + k];
            ls += v; lsq += v * v;
        }
    }
    ls = bsumf(ls); lsq = bsumf(lsq);
    if (t == 0) {
        g_gnp[bc * 2 + 0] = ls;
        g_gnp[bc * 2 + 1] = lsq;
    }
}

// ---------------- GN + GELU + 64x64 projection + residual (champion + batched stage loads) ----------------
#define PROJ_SMEM (64 * 256 * 4 + 64 * 64 * 4)
__global__ void __launch_bounds__(256) k_proj(
        const float* __restrict__ x,
        const float* __restrict__ gn_g, const float* __restrict__ gn_b,
        const float* __restrict__ proj_w, const float* __restrict__ proj_b,
        const float* __restrict__ res_scale, float* __restrict__ out) {
    extern __shared__ __align__(16) float sm[];
    float* As = sm;             // [64][256]
    float* Ws = sm + 64 * 256;  // [c][o] transposed
    int t = threadIdx.x;
    int b = blockIdx.x >> 4;
    int l0 = (blockIdx.x & 15) * 256;

    // inline GN stats from per-(b,c) partials
    float sv_ = 0.f, sq_ = 0.f;
    if (t < 64) {
        sv_ = g_gnp[(b * 64 + t) * 2 + 0];
        sq_ = g_gnp[(b * 64 + t) * 2 + 1];
    }
    float S = bsumf(sv_), Q = bsumf(sq_);
    float n = (float)(CC * LL);
    float mu = S / n;
    float istd = rsqrtf(Q / n - mu * mu + 1e-5f);

    // stage A = gelu(gn(mixed)) with batched loads (2 halves x 8 independent LDG.128)
#pragma unroll
    for (int h = 0; h < 2; h++) {
        float4 mv[8];
        float gg[8], gb[8];
#pragma unroll
        for (int i = 0; i < 8; i++) {
            int idx = t + 256 * (h * 8 + i);
            int c = idx >> 6, j = idx & 63;
            mv[i] = *reinterpret_cast<const float4*>(
                g_mixed + (size_t)(b * 64 + c) * LL + l0 + j * 4);
            gg[i] = gn_g[c]; gb[i] = gn_b[c];
        }
#pragma unroll
        for (int i = 0; i < 8; i++) {
            int idx = t + 256 * (h * 8 + i);
            int c = idx >> 6, j = idx & 63;
            float4 av; float v;
            v = (mv[i].x - mu) * istd * gg[i] + gb[i]; av.x = 0.5f * v * (1.f + erff(v * 0.70710678f));
            v = (mv[i].y - mu) * istd * gg[i] + gb[i]; av.y = 0.5f * v * (1.f + erff(v * 0.70710678f));
            v = (mv[i].z - mu) * istd * gg[i] + gb[i]; av.z = 0.5f * v * (1.f + erff(v * 0.70710678f));
            v = (mv[i].w - mu) * istd * gg[i] + gb[i]; av.w = 0.5f * v * (1.f + erff(v * 0.70710678f));
            *reinterpret_cast<float4*>(As + c * 256 + j * 4) = av;
        }
    }
    for (int idx = t; idx < 4096; idx += 256) {
        int c = idx >> 6, o = idx & 63;
        Ws[c * 64 + o] = proj_w[o * CC + c];
    }
    __syncthreads();

    int to = t >> 4, tl = t & 15;  // 4 outputs (o=to*4..), 16 l (4 quartets at 64q+tl*4)
    ull acc2[4][8];
    ull z2 = pk(0.f, 0.f);
#pragma unroll
    for (int i = 0; i < 4; i++)
#pragma unroll
        for (int p = 0; p < 8; p++) acc2[i][p] = z2;

#pragma unroll 4
    for (int c = 0; c < 64; c++) {
        float4 wv = *reinterpret_cast<const float4*>(Ws + c * 64 + to * 4);
        ull w0 = pk(wv.x, wv.x), w1 = pk(wv.y, wv.y);
        ull w2 = pk(wv.z, wv.z), w3 = pk(wv.w, wv.w);
#pragma unroll
        for (int q = 0; q < 4; q++) {
            ulonglong2 aq = *reinterpret_cast<const ulonglong2*>(
                As + c * 256 + q * 64 + tl * 4);
            fma2(acc2[0][2 * q], w0, aq.x); fma2(acc2[0][2 * q + 1], w0, aq.y);
            fma2(acc2[1][2 * q], w1, aq.x); fma2(acc2[1][2 * q + 1], w1, aq.y);
            fma2(acc2[2][2 * q], w2, aq.x); fma2(acc2[2][2 * q + 1], w2, aq.y);
            fma2(acc2[3][2 * q], w3, aq.x); fma2(acc2[3][2 * q + 1], w3, aq.y);
        }
    }

    float rs = res_scale[0];
#pragma unroll
    for (int i = 0; i < 4; i++) {
        int o = to * 4 + i;
        float pb = proj_b[o];
#pragma unroll
        for (int q = 0; q < 4; q++) {
            float f0, f1, f2, f3;
            upk(f0, f1, acc2[i][2 * q]);
            upk(f2, f3, acc2[i][2 * q + 1]);
            size_t base = ((size_t)(b * 64 + o)) * LL + l0 + q * 64 + tl * 4;
            float4 xv = *reinterpret_cast<const float4*>(x + base);
            float4 ov;
            ov.x = xv.x + rs * (f0 + pb);
            ov.y = xv.y + rs * (f1 + pb);
            ov.z = xv.z + rs * (f2 + pb);
            ov.w = xv.w + rs * (f3 + pb);
            *reinterpret_cast<float4*>(out + base) = ov;
        }
    }
}

// ---------------- launch ----------------
extern "C" void kernel_launch(void* const* d_in, const int* in_sizes, int n_in,
                              void* d_out, int out_size) {
    const float* x       = (const float*)d_in[0];
    const float* dw_w7   = (const float*)d_in[1];
    const float* dw_w15  = (const float*)d_in[2];
    const float* dw_w31  = (const float*)d_in[3];
    const float* dw_w63  = (const float*)d_in[4];
    const float* bn_g    = (const float*)d_in[5];
    const float* bn_b    = (const float*)d_in[6];
    const float* bn_m    = (const float*)d_in[7];
    const float* bn_v    = (const float*)d_in[8];
    const float* comp_w1 = (const float*)d_in[9];
    const float* comp_b1 = (const float*)d_in[10];
    const float* comp_w2 = (const float*)d_in[11];
    const float* comp_b2 = (const float*)d_in[12];
    const float* pn_g    = (const float*)d_in[13];
    const float* pn_b    = (const float*)d_in[14];
    const float* pn_m    = (const float*)d_in[15];
    const float* pn_v    = (const float*)d_in[16];
    const float* pe_w1   = (const float*)d_in[17];
    const float* pe_b1   = (const float*)d_in[18];
    const float* pe_w2   = (const float*)d_in[19];
    const float* pe_b2   = (const float*)d_in[20];
    const float* pg_w    = (const float*)d_in[21];
    const float* pg_b    = (const float*)d_in[22];
    const float* temp    = (const float*)d_in[23];
    const float* gn_g    = (const float*)d_in[24];
    const float* gn_b    = (const float*)d_in[25];
    const float* proj_w  = (const float*)d_in[26];
    const float* proj_b  = (const float*)d_in[27];
    const float* rscale  = (const float*)d_in[28];
    float* out = (float*)d_out;

    cudaFuncSetAttribute(k_proj, cudaFuncAttributeMaxDynamicSharedMemorySize, PROJ_SMEM);

    k_fat<<<BB * CC + BB * 4, 256>>>(x);
    k_gate<<<BB, 256>>>(comp_w1, comp_b1, comp_w2, comp_b2,
                        pn_g, pn_b, pn_m, pn_v,
                        pe_w1, pe_b1, pe_w2, pe_b2, pg_w, pg_b, temp);
    k_conv<<<BB * CC, 256>>>(x, dw_w7, dw_w15, dw_w31, dw_w63,
                             bn_g, bn_b, bn_m, bn_v);
    k_proj<<<BB * 16, 256, PROJ_SMEM>>>(x, gn_g, gn_b, proj_w, proj_b, rscale, out);
}

// round 16
// speedup vs baseline: 1.1491x; 1.0588x over previous
#include <cuda_runtime.h>
#include <math.h>

#define BB 32
#define CC 64
#define LL 4096
#define NHALF 2048
#define PADI(i) ((i) + ((i) >> 5))
typedef unsigned long long ull;

// ---------------- f32x2 helpers ----------------
__device__ __forceinline__ ull pk(float lo, float hi) {
    ull r; asm("mov.b64 %0, {%1, %2};" : "=l"(r) : "f"(lo), "f"(hi)); return r;
}
__device__ __forceinline__ void upk(float& lo, float& hi, ull v) {
    asm("mov.b64 {%0, %1}, %2;" : "=f"(lo), "=f"(hi) : "l"(v));
}
__device__ __forceinline__ void fma2(ull& a, ull b, ull c) {
    asm("fma.rn.f32x2 %0, %1, %2, %0;" : "+l"(a) : "l"(b), "l"(c));
}

// ---------------- scratch ----------------
static __device__ float  g_percol[BB * CC * 4];   // sumx, max|d1|, max|d2|, zc
static __device__ float  g_specp[BB * CC * 3];    // per-(b,c) tot, cen, hi
static __device__ float  g_weights[BB * 4];
static __device__ float  g_svm[BB * LL];
static __device__ double g_pd[BB * 4 * 4];        // per (b,quarter): s, sq, s2, sq2
static __device__ float  g_pf[BB * 4 * 4];        // pre, post, mx, midmx
static __device__ float  g_gnp[BB * CC * 2];      // per-(b,c) sum, sumsq of mixed
static __device__ float  g_mixed[(size_t)BB * CC * LL];

// ---------------- block reductions ----------------
__device__ __forceinline__ float bsumf(float v) {
    __shared__ float sh[32];
    int lane = threadIdx.x & 31, w = threadIdx.x >> 5;
#pragma unroll
    for (int o = 16; o; o >>= 1) v += __shfl_down_sync(0xffffffffu, v, o);
    __syncthreads();
    if (lane == 0) sh[w] = v;
    __syncthreads();
    if (w == 0) {
        int nw = (blockDim.x + 31) >> 5;
        float t = (lane < nw) ? sh[lane] : 0.f;
#pragma unroll
        for (int o = 16; o; o >>= 1) t += __shfl_down_sync(0xffffffffu, t, o);
        if (lane == 0) sh[0] = t;
    }
    __syncthreads();
    return sh[0];
}

__device__ __forceinline__ double bsumd(double v) {
    __shared__ double shd[32];
    int lane = threadIdx.x & 31, w = threadIdx.x >> 5;
#pragma unroll
    for (int o = 16; o; o >>= 1) v += __shfl_down_sync(0xffffffffu, v, o);
    __syncthreads();
    if (lane == 0) shd[w] = v;
    __syncthreads();
    if (w == 0) {
        int nw = (blockDim.x + 31) >> 5;
        double t = (lane < nw) ? shd[lane] : 0.0;
#pragma unroll
        for (int o = 16; o; o >>= 1) t += __shfl_down_sync(0xffffffffu, t, o);
        if (lane == 0) shd[0] = t;
    }
    __syncthreads();
    return shd[0];
}

__device__ __forceinline__ float bmaxf(float v) {
    __shared__ float shm[32];
    int lane = threadIdx.x & 31, w = threadIdx.x >> 5;
#pragma unroll
    for (int o = 16; o; o >>= 1) v = fmaxf(v, __shfl_down_sync(0xffffffffu, v, o));
    __syncthreads();
    if (lane == 0) shm[w] = v;
    __syncthreads();
    if (w == 0) {
        int nw = (blockDim.x + 31) >> 5;
        float t = (lane < nw) ? shm[lane] : -INFINITY;
#pragma unroll
        for (int o = 16; o; o >>= 1) t = fmaxf(t, __shfl_down_sync(0xffffffffu, t, o));
        if (lane == 0) shm[0] = t;
    }
    __syncthreads();
    return shm[0];
}

// ---------------- fused 4-value reductions (256-thread blocks, 8 warps) ----------------
// components x,y: sum; z,w: max. Four interleaved shuffle chains -> ~1 chain latency.
__device__ __forceinline__ float4 bred_ssmm(float4 v) {
    __shared__ float4 sh4[8];
    int lane = threadIdx.x & 31, w = threadIdx.x >> 5;
#pragma unroll
    for (int o = 16; o; o >>= 1) {
        v.x += __shfl_down_sync(0xffffffffu, v.x, o);
        v.y += __shfl_down_sync(0xffffffffu, v.y, o);
        v.z = fmaxf(v.z, __shfl_down_sync(0xffffffffu, v.z, o));
        v.w = fmaxf(v.w, __shfl_down_sync(0xffffffffu, v.w, o));
    }
    __syncthreads();
    if (lane == 0) sh4[w] = v;
    __syncthreads();
    if (w == 0) {
        float4 t = (lane < 8) ? sh4[lane] : make_float4(0.f, 0.f, 0.f, 0.f);
#pragma unroll
        for (int o = 4; o; o >>= 1) {
            t.x += __shfl_down_sync(0xffffffffu, t.x, o);
            t.y += __shfl_down_sync(0xffffffffu, t.y, o);
            t.z = fmaxf(t.z, __shfl_down_sync(0xffffffffu, t.z, o));
            t.w = fmaxf(t.w, __shfl_down_sync(0xffffffffu, t.w, o));
        }
        if (lane == 0) sh4[0] = t;
    }
    __syncthreads();
    return sh4[0];
}

// all four components: sum
__device__ __forceinline__ float4 bred_ssss(float4 v) {
    __shared__ float4 sh4b[8];
    int lane = threadIdx.x & 31, w = threadIdx.x >> 5;
#pragma unroll
    for (int o = 16; o; o >>= 1) {
        v.x += __shfl_down_sync(0xffffffffu, v.x, o);
        v.y += __shfl_down_sync(0xffffffffu, v.y, o);
        v.z += __shfl_down_sync(0xffffffffu, v.z, o);
        v.w += __shfl_down_sync(0xffffffffu, v.w, o);
    }
    __syncthreads();
    if (lane == 0) sh4b[w] = v;
    __syncthreads();
    if (w == 0) {
        float4 t = (lane < 8) ? sh4b[lane] : make_float4(0.f, 0.f, 0.f, 0.f);
#pragma unroll
        for (int o = 4; o; o >>= 1) {
            t.x += __shfl_down_sync(0xffffffffu, t.x, o);
            t.y += __shfl_down_sync(0xffffffffu, t.y, o);
            t.z += __shfl_down_sync(0xffffffffu, t.z, o);
            t.w += __shfl_down_sync(0xffffffffu, t.w, o);
        }
        if (lane == 0) sh4b[0] = t;
    }
    __syncthreads();
    return sh4b[0];
}

// ---------------- FFT butterflies ----------------
__device__ __forceinline__ void bf(float2& u, float2& v, float2 w) {
    float ux = u.x, uy = u.y;
    u.x = ux + v.x; u.y = uy + v.y;
    float dx = ux - v.x, dy = uy - v.y;
    v.x = dx * w.x - dy * w.y;
    v.y = dx * w.y + dy * w.x;
}
__device__ __forceinline__ void bf1(float2& u, float2& v) {
    float ux = u.x, uy = u.y;
    u.x = ux + v.x; u.y = uy + v.y;
    v.x = ux - v.x; v.y = uy - v.y;
}
__device__ __forceinline__ void bfmi(float2& u, float2& v) {
    float ux = u.x, uy = u.y;
    u.x = ux + v.x; u.y = uy + v.y;
    float dx = ux - v.x, dy = uy - v.y;
    v.x = dy; v.y = -dx;
}

// ---------------- fat kernel: blocks [0,2048) = FFT+percol, [2048,2176) = svm ----------------
__global__ void __launch_bounds__(256) k_fat(const float* __restrict__ x) {
    __shared__ float2 Z[PADI(2047) + 1 + 8];
    __shared__ float2 TW[1025];
    int t = threadIdx.x;

    if (blockIdx.x < BB * CC) {
        // ======================= FFT branch =======================
        int bc = blockIdx.x;
        const float* xr = x + (size_t)bc * LL;

        for (int e = t; e < 1025; e += 256) {
            float sn, cs;
            __sincosf(-3.14159265358979f * (float)e / 1024.f, &sn, &cs);
            TW[e] = make_float2(cs, sn);
        }

        float2 r[8];
        float psum = 0.f, m1 = 0.f, m2 = 0.f, zc = 0.f;
#pragma unroll
        for (int j = 0; j < 8; j++) {
            int idx = t + 256 * j;
            float x0 = xr[2 * idx], x1 = xr[2 * idx + 1];
            r[j] = make_float2(x0, x1);
            psum += x0 + x1;
            m1 = fmaxf(m1, fabsf(x1 - x0));
            if (x0 * x1 < 0.f) zc += 1.f;
            if (idx < 2047) {
                float x2 = xr[2 * idx + 2], x3 = xr[2 * idx + 3];
                m1 = fmaxf(m1, fabsf(x2 - x1));
                if (x1 * x2 < 0.f) zc += 1.f;
                m2 = fmaxf(m2, fabsf(x2 - 2.f * x1 + x0));
                m2 = fmaxf(m2, fabsf(x3 - 2.f * x2 + x1));
            }
        }
        float4 rr = bred_ssmm(make_float4(psum, zc, m1, m2));
        if (t == 0) {
            float* p = g_percol + bc * 4;
            p[0] = rr.x; p[1] = rr.z; p[2] = rr.w; p[3] = rr.y;
        }
        __syncthreads();

        // group 1: h = 1024, 512, 256
#pragma unroll
        for (int j = 0; j < 4; j++) bf(r[j], r[j + 4], TW[t + 256 * j]);
        bf(r[0], r[2], TW[2 * t]);   bf(r[1], r[3], TW[2 * t + 512]);
        bf(r[4], r[6], TW[2 * t]);   bf(r[5], r[7], TW[2 * t + 512]);
        bf(r[0], r[1], TW[4 * t]);   bf(r[2], r[3], TW[4 * t]);
        bf(r[4], r[5], TW[4 * t]);   bf(r[6], r[7], TW[4 * t]);
#pragma unroll
        for (int j = 0; j < 8; j++) Z[PADI(t + 256 * j)] = r[j];
        __syncthreads();

        // group 2: h = 128, 64, 32
        {
            int g = t >> 5, u = t & 31;
            int base = g * 256 + u;
#pragma unroll
            for (int j = 0; j < 8; j++) r[j] = Z[PADI(base + 32 * j)];
#pragma unroll
            for (int j = 0; j < 4; j++) bf(r[j], r[j + 4], TW[8 * (u + 32 * j)]);
            bf(r[0], r[2], TW[16 * u]);      bf(r[1], r[3], TW[16 * (u + 32)]);
            bf(r[4], r[6], TW[16 * u]);      bf(r[5], r[7], TW[16 * (u + 32)]);
            bf(r[0], r[1], TW[32 * u]);      bf(r[2], r[3], TW[32 * u]);
            bf(r[4], r[5], TW[32 * u]);      bf(r[6], r[7], TW[32 * u]);
#pragma unroll
            for (int j = 0; j < 8; j++) Z[PADI(base + 32 * j)] = r[j];
        }
        __syncthreads();

        // group 3: h = 16, 8, 4
        {
            int q = t >> 2, v = t & 3;
            int base = q * 32 + v;
#pragma unroll
            for (int j = 0; j < 8; j++) r[j] = Z[PADI(base + 4 * j)];
#pragma unroll
            for (int j = 0; j < 4; j++) bf(r[j], r[j + 4], TW[64 * (v + 4 * j)]);
            bf(r[0], r[2], TW[128 * v]);     bf(r[1], r[3], TW[128 * (v + 4)]);
            bf(r[4], r[6], TW[128 * v]);     bf(r[5], r[7], TW[128 * (v + 4)]);
            bf(r[0], r[1], TW[256 * v]);     bf(r[2], r[3], TW[256 * v]);
            bf(r[4], r[5], TW[256 * v]);     bf(r[6], r[7], TW[256 * v]);
#pragma unroll
            for (int j = 0; j < 8; j++) Z[PADI(base + 4 * j)] = r[j];
        }
        __syncthreads();

        // group 4: h = 2, 1; scatter to natural order
        {
#pragma unroll
            for (int j = 0; j < 8; j++) r[j] = Z[PADI(8 * t + j)];
            bf1(r[0], r[2]); bfmi(r[1], r[3]);
            bf1(r[4], r[6]); bfmi(r[5], r[7]);
            bf1(r[0], r[1]); bf1(r[2], r[3]);
            bf1(r[4], r[5]); bf1(r[6], r[7]);
            int rev8t = (int)(__brev((unsigned)t) >> 24);
            const int rev3[8] = {0, 4, 2, 6, 1, 5, 3, 7};
            __syncthreads();
#pragma unroll
            for (int j = 0; j < 8; j++)
                Z[PADI((rev3[j] << 8) | rev8t)] = r[j];
        }
        __syncthreads();

        // unpack real bins via TW table (even k: TW[k/2]; odd k: TW[k/2] * rot)
        float rsn, rc;
        __sincosf(-3.14159265358979f / 2048.f, &rsn, &rc);
        float tot = 0.f, cen = 0.f, hi = 0.f;
        for (int k = t; k <= NHALF; k += 256) {
            int ik = k & (NHALF - 1);
            int im = (NHALF - k) & (NHALF - 1);
            float2 Zk = Z[PADI(ik)], Zm = Z[PADI(im)];
            float zex = 0.5f * (Zk.x + Zm.x), zey = 0.5f * (Zk.y - Zm.y);
            float zox = 0.5f * (Zk.y + Zm.y), zoy = -0.5f * (Zk.x - Zm.x);
            float2 w = TW[k >> 1];
            float rcc = (k & 1) ? rc : 1.f;
            float rss = (k & 1) ? rsn : 0.f;
            float wx = w.x * rcc - w.y * rss;
            float wy = w.x * rss + w.y * rcc;
            float Xr = zex + wx * zox - wy * zoy;
            float Xi = zey + wx * zoy + wy * zox;
            float p = (Xr * Xr + Xi * Xi) * (1.f / 4096.f);
            tot += p;
            cen += p * ((float)k * (1.f / 2048.f));
            if (k >= 820) hi += p;
        }
        float4 ss = bred_ssss(make_float4(tot, cen, hi, 0.f));
        if (t == 0) {
            float* sp = g_specp + bc * 3;
            sp[0] = ss.x; sp[1] = ss.y; sp[2] = ss.z;
        }
    } else {
        // ======================= svm branch =======================
        int idx = blockIdx.x - BB * CC;
        int b = idx >> 2, quarter = idx & 3;
        int l0 = quarter * 1024 + t * 4;
        const float* xb = x + (size_t)b * CC * LL;

        ull a01 = pk(0.f, 0.f), a23 = a01;
#pragma unroll
        for (int c = 0; c < CC; c++) {
            ulonglong2 v2 = *reinterpret_cast<const ulonglong2*>(xb + (size_t)c * LL + l0);
            fma2(a01, v2.x, v2.x);
            fma2(a23, v2.y, v2.y);
        }
        float q0, q1, q2, q3;
        upk(q0, q1, a01); upk(q2, q3, a23);
        float sv[4] = {sqrtf(q0), sqrtf(q1), sqrtf(q2), sqrtf(q3)};
        *reinterpret_cast<float4*>(g_svm + b * LL + l0) =
            make_float4(sv[0], sv[1], sv[2], sv[3]);

        double s = 0, sq = 0, s2 = 0, sq2 = 0;
        float pre = 0.f, post = 0.f, mx = 0.f, mid = 0.f;
#pragma unroll
        for (int k = 0; k < 4; k++) {
            int l = l0 + k;
            float v = sv[k];
            s += v; sq += (double)v * v;
            if (l >= 2048) { s2 += v; sq2 += (double)v * v; }
            if (l < 1365)      pre += v;
            else if (l < 2730) mid = fmaxf(mid, v);
            else               post += v;
            mx = fmaxf(mx, v);
        }
        s = bsumd(s); sq = bsumd(sq); s2 = bsumd(s2); sq2 = bsumd(sq2);
        float4 pp = bred_ssmm(make_float4(pre, post, mx, mid));
        if (t == 0) {
            double* pd = g_pd + idx * 4;
            pd[0] = s; pd[1] = sq; pd[2] = s2; pd[3] = sq2;
            float* pf = g_pf + idx * 4;
            pf[0] = pp.x; pf[1] = pp.y; pf[2] = pp.z; pf[3] = pp.w;
        }
    }
}

// ---------------- gate: svm finalize + counts + MLPs -> weights ----------------
__global__ void __launch_bounds__(256) k_gate(
        const float* __restrict__ comp_w1, const float* __restrict__ comp_b1,
        const float* __restrict__ comp_w2, const float* __restrict__ comp_b2,
        const float* __restrict__ pn_g, const float* __restrict__ pn_b,
        const float* __restrict__ pn_m, const float* __restrict__ pn_v,
        const float* __restrict__ pe_w1, const float* __restrict__ pe_b1,
        const float* __restrict__ pe_w2, const float* __restrict__ pe_b2,
        const float* __restrict__ pg_w, const float* __restrict__ pg_b,
        const float* __restrict__ temperature) {
    int b = blockIdx.x, t = threadIdx.x;
    __shared__ float xm[CC], h[CC], p1[32], p2[32], pf[12], zz[4];
    __shared__ float sthr[3], sf[4];

    if (t == 0) {
        double s = 0, sq = 0, s2 = 0, sq2 = 0;
        float pre = 0, post = 0, mx = 0, mid = 0;
        for (int q = 0; q < 4; q++) {
            const double* pd = g_pd + (b * 4 + q) * 4;
            s += pd[0]; sq += pd[1]; s2 += pd[2]; sq2 += pd[3];
            const float* pp = g_pf + (b * 4 + q) * 4;
            pre += pp[0]; post += pp[1];
            mx = fmaxf(mx, pp[2]); mid = fmaxf(mid, pp[3]);
        }
        float mean = (float)(s / LL);
        float var1 = (float)((sq - s * s / LL) / (LL - 1));
        float sdev = sqrtf(fmaxf(var1, 0.f)) + 1e-6f;
        sthr[0] = mean + 2.f * sdev;
        sthr[1] = mean + 3.f * sdev;
        sthr[2] = mean - sdev;
        sf[0] = mx; sf[1] = mean;
        double var2 = (sq2 - s2 * s2 / NHALF) / (NHALF - 1);
        float std2 = sqrtf(fmaxf((float)var2, 0.f));
        sf[2] = tanhf(1.f / (std2 + 1e-6f));
        float prem = pre / 1365.f, postm = post / 1366.f;
        float fp = fmaxf(mid - prem, 0.f) + fmaxf(mid - postm, 0.f);
        sf[3] = fp / (fabsf(mid) + 1e-6f);
    }
    __syncthreads();

    float thr = sthr[0], hthr = sthr[1], lthr = sthr[2];
    float c1 = 0.f, c2 = 0.f, c3 = 0.f;
    const float* sr = g_svm + b * LL;
    for (int l = t; l < LL; l += 256) {
        float sv = sr[l];
        if (sv > thr)  c1 += 1.f;
        if (sv > hthr) c2 += 1.f;
        if (sv < lthr) c3 += 1.f;
    }
    c1 = bsumf(c1); c2 = bsumf(c2); c3 = bsumf(c3);

    float tpv = 0, cnv = 0, hiv = 0, jmv = 0, jrv = 0, zcv = 0;
    if (t < 64) {
        const float* sp = g_specp + (b * 64 + t) * 3;
        tpv = sp[0]; cnv = sp[1]; hiv = sp[2];
        const float* pc = g_percol + (b * 64 + t) * 4;
        xm[t] = pc[0] * (1.f / LL);
        jmv = pc[1]; jrv = pc[2]; zcv = pc[3];
    }
    float tp = bsumf(tpv), cn = bsumf(cnv), hh = bsumf(hiv);
    float jm = bsumf(jmv), jr = bsumf(jrv), zc = bsumf(zcv);

    if (t == 0) {
        float f[12];
        f[0] = sf[0]; f[1] = sf[1]; f[7] = sf[2]; f[11] = sf[3];
        f[2] = jm * (1.f / CC) * 50.f;
        f[3] = jr * (1.f / CC) * 2500.f;
        f[4] = zc * (1.f / CC) * (1.f / LL);
        f[5] = c1 / LL; f[6] = c2 / LL; f[8] = c3 / LL;
        f[9] = cn / (tp + 1e-6f);
        f[10] = hh / (tp + 1e-6f);
        for (int i = 0; i < 12; i++) {
            float v = f[i];
            if (!isfinite(v)) v = 0.f;
            pf[i] = (v - pn_m[i]) * rsqrtf(pn_v[i] + 1e-5f) * pn_g[i] + pn_b[i];
        }
    }
    __syncthreads();

    if (t < 64) {
        float acc = comp_b1[t];
        for (int c = 0; c < CC; c++) acc = fmaf(xm[c], comp_w1[c * CC + t], acc);
        h[t] = fmaxf(acc, 0.f);
        if (t < 32) {
            float q1 = pe_b1[t];
            for (int i = 0; i < 12; i++) q1 = fmaf(pf[i], pe_w1[i * 32 + t], q1);
            p1[t] = fmaxf(q1, 0.f);
        }
    }
    __syncthreads();
    if (t < 32) {
        float q2 = pe_b2[t];
        for (int i = 0; i < 32; i++) q2 = fmaf(p1[i], pe_w2[i * 32 + t], q2);
        p2[t] = fmaxf(q2, 0.f);
    }
    __syncthreads();
    if (t < 4) {
        float lg = comp_b2[t];
        for (int i = 0; i < CC; i++) lg = fmaf(h[i], comp_w2[i * 4 + t], lg);
        float pg = pg_b[t];
        for (int i = 0; i < 32; i++) pg = fmaf(p2[i], pg_w[i * 4 + t], pg);
        float pw = 1.f / (1.f + expf(-pg));
        float temp = fmaxf(temperature[0], 0.1f);
        zz[t] = lg * pw / temp;
    }
    __syncthreads();
    if (t == 0) {
        float m = fmaxf(fmaxf(zz[0], zz[1]), fmaxf(zz[2], zz[3]));
        float e0 = expf(zz[0] - m), e1 = expf(zz[1] - m);
        float e2 = expf(zz[2] - m), e3 = expf(zz[3] - m);
        float si = 1.f / (e0 + e1 + e2 + e3);
        g_weights[b * 4 + 0] = e0 * si;
        g_weights[b * 4 + 1] = e1 * si;
        g_weights[b * 4 + 2] = e2 * si;
        g_weights[b * 4 + 3] = e3 * si;
    }
}

// ---------------- combined 63-tap conv with f32x2 dual-parity window ----------------
#define XS_LEN (LL + 62 + 8)
__global__ void __launch_bounds__(256) k_conv(
        const float* __restrict__ x,
        const float* __restrict__ w7, const float* __restrict__ w15,
        const float* __restrict__ w31, const float* __restrict__ w63,
        const float* __restrict__ bn_g, const float* __restrict__ bn_b,
        const float* __restrict__ bn_m, const float* __restrict__ bn_v) {
    int bc = blockIdx.x;
    int b = bc >> 6, c = bc & 63;
    __shared__ __align__(16) float coef[64];
    __shared__ float sbias;
    __shared__ __align__(16) float xs[XS_LEN];
    int t = threadIdx.x;

    float wk0 = g_weights[b * 4 + 0], wk1 = g_weights[b * 4 + 1];
    float wk2 = g_weights[b * 4 + 2], wk3 = g_weights[b * 4 + 3];
    if (t < 64) {
        float sc0 = bn_g[0 * CC + c] * rsqrtf(bn_v[0 * CC + c] + 1e-5f);
        float sc1 = bn_g[1 * CC + c] * rsqrtf(bn_v[1 * CC + c] + 1e-5f);
        float sc2 = bn_g[2 * CC + c] * rsqrtf(bn_v[2 * CC + c] + 1e-5f);
        float sc3 = bn_g[3 * CC + c] * rsqrtf(bn_v[3 * CC + c] + 1e-5f);
        if (t < 63) {
            int o = t - 31;
            float cf = wk3 * sc3 * w63[c * 63 + t];
            if (o >= -15 && o <= 15) cf += wk2 * sc2 * w31[c * 31 + o + 15];
            if (o >= -7  && o <= 7 ) cf += wk1 * sc1 * w15[c * 15 + o + 7];
            if (o >= -3  && o <= 3 ) cf += wk0 * sc0 * w7 [c * 7  + o + 3];
            coef[t] = cf;
        } else {
            coef[63] = 0.f;
            sbias = wk0 * (bn_b[0 * CC + c] - bn_m[0 * CC + c] * sc0)
                  + wk1 * (bn_b[1 * CC + c] - bn_m[1 * CC + c] * sc1)
                  + wk2 * (bn_b[2 * CC + c] - bn_m[2 * CC + c] * sc2)
                  + wk3 * (bn_b[3 * CC + c] - bn_m[3 * CC + c] * sc3);
        }
    }
    // batched float4 staging: body xs[31 + 4j .. 31 + 4j + 3] = xr4[j]
    const float* xr = x + (size_t)bc * LL;
    const float4* xr4 = reinterpret_cast<const float4*>(xr);
    {
        float4 v[4];
#pragma unroll
        for (int i = 0; i < 4; i++) v[i] = xr4[t + 256 * i];
#pragma unroll
        for (int i = 0; i < 4; i++) {
            int j = t + 256 * i;
            xs[31 + 4 * j + 0] = v[i].x;
            xs[31 + 4 * j + 1] = v[i].y;
            xs[31 + 4 * j + 2] = v[i].z;
            xs[31 + 4 * j + 3] = v[i].w;
        }
        if (t < 31) xs[t] = 0.f;
        if (t < XS_LEN - (31 + LL)) xs[31 + LL + t] = 0.f;
    }
    __syncthreads();

    int o0 = t * 16;
    float bias = sbias;
    ull acc2[8];
    ull bias2 = pk(bias, bias);
#pragma unroll
    for (int m = 0; m < 8; m++) acc2[m] = bias2;

    const float4* xs4 = reinterpret_cast<const float4*>(xs + o0);
    const float4* cf4 = reinterpret_cast<const float4*>(coef);

    ull pE[10], pO[9];
    float last;
    {
        float v[20];
#pragma unroll
        for (int q = 0; q < 5; q++) {
            float4 t4 = xs4[q];
            v[4 * q + 0] = t4.x; v[4 * q + 1] = t4.y;
            v[4 * q + 2] = t4.z; v[4 * q + 3] = t4.w;
        }
#pragma unroll
        for (int k = 0; k < 10; k++) pE[k] = pk(v[2 * k], v[2 * k + 1]);
#pragma unroll
        for (int k = 0; k < 9; k++)  pO[k] = pk(v[2 * k + 1], v[2 * k + 2]);
        last = v[19];
    }

#pragma unroll
    for (int g = 0; g < 16; g++) {
        float4 cv = cf4[g];
        ull c0 = pk(cv.x, cv.x), c1 = pk(cv.y, cv.y);
        ull c2 = pk(cv.z, cv.z), c3 = pk(cv.w, cv.w);
#pragma unroll
        for (int m = 0; m < 8; m++) fma2(acc2[m], c0, pE[m]);
#pragma unroll
        for (int m = 0; m < 8; m++) fma2(acc2[m], c1, pO[m]);
#pragma unroll
        for (int m = 0; m < 8; m++) fma2(acc2[m], c2, pE[m + 1]);
#pragma unroll
        for (int m = 0; m < 8; m++) fma2(acc2[m], c3, pO[m + 1]);
        if (g < 15) {
            float4 nv = xs4[5 + g];
#pragma unroll
            for (int m = 0; m < 8; m++) pE[m] = pE[m + 2];
#pragma unroll
            for (int m = 0; m < 7; m++) pO[m] = pO[m + 2];
            pE[8] = pk(nv.x, nv.y); pE[9] = pk(nv.z, nv.w);
            pO[7] = pk(last, nv.x); pO[8] = pk(nv.y, nv.z);
            last = nv.w;
        }
    }

    float outv[16];
#pragma unroll
    for (int m = 0; m < 8; m++) upk(outv[2 * m], outv[2 * m + 1], acc2[m]);

    float ls = 0.f, lsq = 0.f;
    float* mrow = g_mixed + (size_t)bc * LL + o0;
#pragma unroll
    for (int j = 0; j < 16; j += 4) {
        *reinterpret_cast<float4*>(mrow + j) =
            make_float4(outv[j], outv[j + 1], outv[j + 2], outv[j + 3]);
#pragma unroll
        for (int k = 0; k < 4; k++) {
            float v = outv[j + k];
            ls += v; lsq += v * v;
        }
    }
    float4 gred = bred_ssss(make_float4(ls, lsq, 0.f, 0.f));
    if (t == 0) {
        g_gnp[bc * 2 + 0] = gred.x;
        g_gnp[bc * 2 + 1] = gred.y;
    }
}

// ---------------- GN + GELU + 64x64 projection + residual (champion + batched stage loads) ----------------
#define PROJ_SMEM (64 * 256 * 4 + 64 * 64 * 4)
__global__ void __launch_bounds__(256) k_proj(
        const float* __restrict__ x,
        const float* __restrict__ gn_g, const float* __restrict__ gn_b,
        const float* __restrict__ proj_w, const float* __restrict__ proj_b,
        const float* __restrict__ res_scale, float* __restrict__ out) {
    extern __shared__ __align__(16) float sm[];
    float* As = sm;             // [64][256]
    float* Ws = sm + 64 * 256;  // [c][o] transposed
    int t = threadIdx.x;
    int b = blockIdx.x >> 4;
    int l0 = (blockIdx.x & 15) * 256;

    // inline GN stats from per-(b,c) partials
    float sv_ = 0.f, sq_ = 0.f;
    if (t < 64) {
        sv_ = g_gnp[(b * 64 + t) * 2 + 0];
        sq_ = g_gnp[(b * 64 + t) * 2 + 1];
    }
    float S = bsumf(sv_), Q = bsumf(sq_);
    float n = (float)(CC * LL);
    float mu = S / n;
    float istd = rsqrtf(Q / n - mu * mu + 1e-5f);

    // stage A = gelu(gn(mixed)) with batched loads (2 halves x 8 independent LDG.128)
#pragma unroll
    for (int h = 0; h < 2; h++) {
        float4 mv[8];
        float gg[8], gb[8];
#pragma unroll
        for (int i = 0; i < 8; i++) {
            int idx = t + 256 * (h * 8 + i);
            int c = idx >> 6, j = idx & 63;
            mv[i] = *reinterpret_cast<const float4*>(
                g_mixed + (size_t)(b * 64 + c) * LL + l0 + j * 4);
            gg[i] = gn_g[c]; gb[i] = gn_b[c];
        }
#pragma unroll
        for (int i = 0; i < 8; i++) {
            int idx = t + 256 * (h * 8 + i);
            int c = idx >> 6, j = idx & 63;
            float4 av; float v;
            v = (mv[i].x - mu) * istd * gg[i] + gb[i]; av.x = 0.5f * v * (1.f + erff(v * 0.70710678f));
            v = (mv[i].y - mu) * istd * gg[i] + gb[i]; av.y = 0.5f * v * (1.f + erff(v * 0.70710678f));
            v = (mv[i].z - mu) * istd * gg[i] + gb[i]; av.z = 0.5f * v * (1.f + erff(v * 0.70710678f));
            v = (mv[i].w - mu) * istd * gg[i] + gb[i]; av.w = 0.5f * v * (1.f + erff(v * 0.70710678f));
            *reinterpret_cast<float4*>(As + c * 256 + j * 4) = av;
        }
    }
    for (int idx = t; idx < 4096; idx += 256) {
        int c = idx >> 6, o = idx & 63;
        Ws[c * 64 + o] = proj_w[o * CC + c];
    }
    __syncthreads();

    int to = t >> 4, tl = t & 15;  // 4 outputs (o=to*4..), 16 l (4 quartets at 64q+tl*4)
    ull acc2[4][8];
    ull z2 = pk(0.f, 0.f);
#pragma unroll
    for (int i = 0; i < 4; i++)
#pragma unroll
        for (int p = 0; p < 8; p++) acc2[i][p] = z2;

#pragma unroll 4
    for (int c = 0; c < 64; c++) {
        float4 wv = *reinterpret_cast<const float4*>(Ws + c * 64 + to * 4);
        ull w0 = pk(wv.x, wv.x), w1 = pk(wv.y, wv.y);
        ull w2 = pk(wv.z, wv.z), w3 = pk(wv.w, wv.w);
#pragma unroll
        for (int q = 0; q < 4; q++) {
            ulonglong2 aq = *reinterpret_cast<const ulonglong2*>(
                As + c * 256 + q * 64 + tl * 4);
            fma2(acc2[0][2 * q], w0, aq.x); fma2(acc2[0][2 * q + 1], w0, aq.y);
            fma2(acc2[1][2 * q], w1, aq.x); fma2(acc2[1][2 * q + 1], w1, aq.y);
            fma2(acc2[2][2 * q], w2, aq.x); fma2(acc2[2][2 * q + 1], w2, aq.y);
            fma2(acc2[3][2 * q], w3, aq.x); fma2(acc2[3][2 * q + 1], w3, aq.y);
        }
    }

    float rs = res_scale[0];
#pragma unroll
    for (int i = 0; i < 4; i++) {
        int o = to * 4 + i;
        float pb = proj_b[o];
#pragma unroll
        for (int q = 0; q < 4; q++) {
            float f0, f1, f2, f3;
            upk(f0, f1, acc2[i][2 * q]);
            upk(f2, f3, acc2[i][2 * q + 1]);
            size_t base = ((size_t)(b * 64 + o)) * LL + l0 + q * 64 + tl * 4;
            float4 xv = *reinterpret_cast<const float4*>(x + base);
            float4 ov;
            ov.x = xv.x + rs * (f0 + pb);
            ov.y = xv.y + rs * (f1 + pb);
            ov.z = xv.z + rs * (f2 + pb);
            ov.w = xv.w + rs * (f3 + pb);
            *reinterpret_cast<float4*>(out + base) = ov;
        }
    }
}

// ---------------- launch ----------------
extern "C" void kernel_launch(void* const* d_in, const int* in_sizes, int n_in,
                              void* d_out, int out_size) {
    const float* x       = (const float*)d_in[0];
    const float* dw_w7   = (const float*)d_in[1];
    const float* dw_w15  = (const float*)d_in[2];
    const float* dw_w31  = (const float*)d_in[3];
    const float* dw_w63  = (const float*)d_in[4];
    const float* bn_g    = (const float*)d_in[5];
    const float* bn_b    = (const float*)d_in[6];
    const float* bn_m    = (const float*)d_in[7];
    const float* bn_v    = (const float*)d_in[8];
    const float* comp_w1 = (const float*)d_in[9];
    const float* comp_b1 = (const float*)d_in[10];
    const float* comp_w2 = (const float*)d_in[11];
    const float* comp_b2 = (const float*)d_in[12];
    const float* pn_g    = (const float*)d_in[13];
    const float* pn_b    = (const float*)d_in[14];
    const float* pn_m    = (const float*)d_in[15];
    const float* pn_v    = (const float*)d_in[16];
    const float* pe_w1   = (const float*)d_in[17];
    const float* pe_b1   = (const float*)d_in[18];
    const float* pe_w2   = (const float*)d_in[19];
    const float* pe_b2   = (const float*)d_in[20];
    const float* pg_w    = (const float*)d_in[21];
    const float* pg_b    = (const float*)d_in[22];
    const float* temp    = (const float*)d_in[23];
    const float* gn_g    = (const float*)d_in[24];
    const float* gn_b    = (const float*)d_in[25];
    const float* proj_w  = (const float*)d_in[26];
    const float* proj_b  = (const float*)d_in[27];
    const float* rscale  = (const float*)d_in[28];
    float* out = (float*)d_out;

    cudaFuncSetAttribute(k_proj, cudaFuncAttributeMaxDynamicSharedMemorySize, PROJ_SMEM);

    k_fat<<<BB * CC + BB * 4, 256>>>(x);
    k_gate<<<BB, 256>>>(comp_w1, comp_b1, comp_w2, comp_b2,
                        pn_g, pn_b, pn_m, pn_v,
                        pe_w1, pe_b1, pe_w2, pe_b2, pg_w, pg_b, temp);
    k_conv<<<BB * CC, 256>>>(x, dw_w7, dw_w15, dw_w31, dw_w63,
                             bn_g, bn_b, bn_m, bn_v);
    k_proj<<<BB * 16, 256, PROJ_SMEM>>>(x, gn_g, gn_b, proj_w, proj_b, rscale, out);
}

// round 17
// speedup vs baseline: 1.1711x; 1.0192x over previous
#include <cuda_runtime.h>
#include <math.h>

#define BB 32
#define CC 64
#define LL 4096
#define NHALF 2048
#define PADI(i) ((i) + ((i) >> 5))
typedef unsigned long long ull;

// ---------------- f32x2 helpers ----------------
__device__ __forceinline__ ull pk(float lo, float hi) {
    ull r; asm("mov.b64 %0, {%1, %2};" : "=l"(r) : "f"(lo), "f"(hi)); return r;
}
__device__ __forceinline__ void upk(float& lo, float& hi, ull v) {
    asm("mov.b64 {%0, %1}, %2;" : "=f"(lo), "=f"(hi) : "l"(v));
}
__device__ __forceinline__ void fma2(ull& a, ull b, ull c) {
    asm("fma.rn.f32x2 %0, %1, %2, %0;" : "+l"(a) : "l"(b), "l"(c));
}

// ---------------- scratch ----------------
static __device__ float  g_percol[BB * CC * 4];   // sumx, max|d1|, max|d2|, zc
static __device__ float  g_specp[BB * CC * 3];    // per-(b,c) tot, cen, hi
static __device__ float  g_weights[BB * 4];
static __device__ float  g_svm[BB * LL];
static __device__ double g_pd[BB * 4 * 4];        // per (b,quarter): s, sq, s2, sq2
static __device__ float  g_pf[BB * 4 * 4];        // pre, post, mx, midmx
static __device__ float  g_gnp[BB * CC * 2];      // per-(b,c) sum, sumsq of mixed
static __device__ float  g_mixed[(size_t)BB * CC * LL];

// ---------------- block reductions ----------------
__device__ __forceinline__ float bsumf(float v) {
    __shared__ float sh[32];
    int lane = threadIdx.x & 31, w = threadIdx.x >> 5;
#pragma unroll
    for (int o = 16; o; o >>= 1) v += __shfl_down_sync(0xffffffffu, v, o);
    __syncthreads();
    if (lane == 0) sh[w] = v;
    __syncthreads();
    if (w == 0) {
        int nw = (blockDim.x + 31) >> 5;
        float t = (lane < nw) ? sh[lane] : 0.f;
#pragma unroll
        for (int o = 16; o; o >>= 1) t += __shfl_down_sync(0xffffffffu, t, o);
        if (lane == 0) sh[0] = t;
    }
    __syncthreads();
    return sh[0];
}

__device__ __forceinline__ double bsumd(double v) {
    __shared__ double shd[32];
    int lane = threadIdx.x & 31, w = threadIdx.x >> 5;
#pragma unroll
    for (int o = 16; o; o >>= 1) v += __shfl_down_sync(0xffffffffu, v, o);
    __syncthreads();
    if (lane == 0) shd[w] = v;
    __syncthreads();
    if (w == 0) {
        int nw = (blockDim.x + 31) >> 5;
        double t = (lane < nw) ? shd[lane] : 0.0;
#pragma unroll
        for (int o = 16; o; o >>= 1) t += __shfl_down_sync(0xffffffffu, t, o);
        if (lane == 0) shd[0] = t;
    }
    __syncthreads();
    return shd[0];
}

// ---------------- fused 4-value reductions (256-thread blocks, 8 warps) ----------------
__device__ __forceinline__ float4 bred_ssmm(float4 v) {
    __shared__ float4 sh4[8];
    int lane = threadIdx.x & 31, w = threadIdx.x >> 5;
#pragma unroll
    for (int o = 16; o; o >>= 1) {
        v.x += __shfl_down_sync(0xffffffffu, v.x, o);
        v.y += __shfl_down_sync(0xffffffffu, v.y, o);
        v.z = fmaxf(v.z, __shfl_down_sync(0xffffffffu, v.z, o));
        v.w = fmaxf(v.w, __shfl_down_sync(0xffffffffu, v.w, o));
    }
    __syncthreads();
    if (lane == 0) sh4[w] = v;
    __syncthreads();
    if (w == 0) {
        float4 t = (lane < 8) ? sh4[lane] : make_float4(0.f, 0.f, 0.f, 0.f);
#pragma unroll
        for (int o = 4; o; o >>= 1) {
            t.x += __shfl_down_sync(0xffffffffu, t.x, o);
            t.y += __shfl_down_sync(0xffffffffu, t.y, o);
            t.z = fmaxf(t.z, __shfl_down_sync(0xffffffffu, t.z, o));
            t.w = fmaxf(t.w, __shfl_down_sync(0xffffffffu, t.w, o));
        }
        if (lane == 0) sh4[0] = t;
    }
    __syncthreads();
    return sh4[0];
}

__device__ __forceinline__ float4 bred_ssss(float4 v) {
    __shared__ float4 sh4b[8];
    int lane = threadIdx.x & 31, w = threadIdx.x >> 5;
#pragma unroll
    for (int o = 16; o; o >>= 1) {
        v.x += __shfl_down_sync(0xffffffffu, v.x, o);
        v.y += __shfl_down_sync(0xffffffffu, v.y, o);
        v.z += __shfl_down_sync(0xffffffffu, v.z, o);
        v.w += __shfl_down_sync(0xffffffffu, v.w, o);
    }
    __syncthreads();
    if (lane == 0) sh4b[w] = v;
    __syncthreads();
    if (w == 0) {
        float4 t = (lane < 8) ? sh4b[lane] : make_float4(0.f, 0.f, 0.f, 0.f);
#pragma unroll
        for (int o = 4; o; o >>= 1) {
            t.x += __shfl_down_sync(0xffffffffu, t.x, o);
            t.y += __shfl_down_sync(0xffffffffu, t.y, o);
            t.z += __shfl_down_sync(0xffffffffu, t.z, o);
            t.w += __shfl_down_sync(0xffffffffu, t.w, o);
        }
        if (lane == 0) sh4b[0] = t;
    }
    __syncthreads();
    return sh4b[0];
}

// ---------------- FFT butterflies ----------------
__device__ __forceinline__ void bf(float2& u, float2& v, float2 w) {
    float ux = u.x, uy = u.y;
    u.x = ux + v.x; u.y = uy + v.y;
    float dx = ux - v.x, dy = uy - v.y;
    v.x = dx * w.x - dy * w.y;
    v.y = dx * w.y + dy * w.x;
}
__device__ __forceinline__ void bf1(float2& u, float2& v) {
    float ux = u.x, uy = u.y;
    u.x = ux + v.x; u.y = uy + v.y;
    v.x = ux - v.x; v.y = uy - v.y;
}
__device__ __forceinline__ void bfmi(float2& u, float2& v) {
    float ux = u.x, uy = u.y;
    u.x = ux + v.x; u.y = uy + v.y;
    float dx = ux - v.x, dy = uy - v.y;
    v.x = dy; v.y = -dx;
}

// ---------------- fat kernel: blocks [0,2048) = FFT+percol, [2048,2176) = svm ----------------
__global__ void __launch_bounds__(256) k_fat(const float* __restrict__ x) {
    __shared__ float2 Z[PADI(2047) + 1 + 8];
    __shared__ float2 TW[1025];
    int t = threadIdx.x;

    if (blockIdx.x < BB * CC) {
        // ======================= FFT branch =======================
        int bc = blockIdx.x;
        const float* xr = x + (size_t)bc * LL;

        for (int e = t; e < 1025; e += 256) {
            float sn, cs;
            __sincosf(-3.14159265358979f * (float)e / 1024.f, &sn, &cs);
            TW[e] = make_float2(cs, sn);
        }

        // batched loads: 8 main pairs + 8 neighbor pairs, then stats
        float2 r[8], q[8];
#pragma unroll
        for (int j = 0; j < 8; j++) {
            int idx = t + 256 * j;
            r[j] = *reinterpret_cast<const float2*>(xr + 2 * idx);
        }
#pragma unroll
        for (int j = 0; j < 8; j++) {
            int idx = t + 256 * j;
            int a = (idx < 2047) ? (2 * idx + 2) : 4094;   // clamped (dummy for last)
            q[j] = *reinterpret_cast<const float2*>(xr + a);
        }
        float psum = 0.f, m1 = 0.f, m2 = 0.f, zc = 0.f;
#pragma unroll
        for (int j = 0; j < 8; j++) {
            int idx = t + 256 * j;
            float x0 = r[j].x, x1 = r[j].y;
            psum += x0 + x1;
            m1 = fmaxf(m1, fabsf(x1 - x0));
            if (x0 * x1 < 0.f) zc += 1.f;
            if (idx < 2047) {
                float x2 = q[j].x, x3 = q[j].y;
                m1 = fmaxf(m1, fabsf(x2 - x1));
                if (x1 * x2 < 0.f) zc += 1.f;
                m2 = fmaxf(m2, fabsf(x2 - 2.f * x1 + x0));
                m2 = fmaxf(m2, fabsf(x3 - 2.f * x2 + x1));
            }
        }
        float4 rr = bred_ssmm(make_float4(psum, zc, m1, m2));
        if (t == 0) {
            float* p = g_percol + bc * 4;
            p[0] = rr.x; p[1] = rr.z; p[2] = rr.w; p[3] = rr.y;
        }
        __syncthreads();

        // group 1: h = 1024, 512, 256
#pragma unroll
        for (int j = 0; j < 4; j++) bf(r[j], r[j + 4], TW[t + 256 * j]);
        bf(r[0], r[2], TW[2 * t]);   bf(r[1], r[3], TW[2 * t + 512]);
        bf(r[4], r[6], TW[2 * t]);   bf(r[5], r[7], TW[2 * t + 512]);
        bf(r[0], r[1], TW[4 * t]);   bf(r[2], r[3], TW[4 * t]);
        bf(r[4], r[5], TW[4 * t]);   bf(r[6], r[7], TW[4 * t]);
#pragma unroll
        for (int j = 0; j < 8; j++) Z[PADI(t + 256 * j)] = r[j];
        __syncthreads();

        // group 2: h = 128, 64, 32
        {
            int g = t >> 5, u = t & 31;
            int base = g * 256 + u;
#pragma unroll
            for (int j = 0; j < 8; j++) r[j] = Z[PADI(base + 32 * j)];
#pragma unroll
            for (int j = 0; j < 4; j++) bf(r[j], r[j + 4], TW[8 * (u + 32 * j)]);
            bf(r[0], r[2], TW[16 * u]);      bf(r[1], r[3], TW[16 * (u + 32)]);
            bf(r[4], r[6], TW[16 * u]);      bf(r[5], r[7], TW[16 * (u + 32)]);
            bf(r[0], r[1], TW[32 * u]);      bf(r[2], r[3], TW[32 * u]);
            bf(r[4], r[5], TW[32 * u]);      bf(r[6], r[7], TW[32 * u]);
#pragma unroll
            for (int j = 0; j < 8; j++) Z[PADI(base + 32 * j)] = r[j];
        }
        __syncthreads();

        // group 3: h = 16, 8, 4
        {
            int q3 = t >> 2, v = t & 3;
            int base = q3 * 32 + v;
#pragma unroll
            for (int j = 0; j < 8; j++) r[j] = Z[PADI(base + 4 * j)];
#pragma unroll
            for (int j = 0; j < 4; j++) bf(r[j], r[j + 4], TW[64 * (v + 4 * j)]);
            bf(r[0], r[2], TW[128 * v]);     bf(r[1], r[3], TW[128 * (v + 4)]);
            bf(r[4], r[6], TW[128 * v]);     bf(r[5], r[7], TW[128 * (v + 4)]);
            bf(r[0], r[1], TW[256 * v]);     bf(r[2], r[3], TW[256 * v]);
            bf(r[4], r[5], TW[256 * v]);     bf(r[6], r[7], TW[256 * v]);
#pragma unroll
            for (int j = 0; j < 8; j++) Z[PADI(base + 4 * j)] = r[j];
        }
        __syncthreads();

        // group 4: h = 2, 1; scatter to natural order
        {
#pragma unroll
            for (int j = 0; j < 8; j++) r[j] = Z[PADI(8 * t + j)];
            bf1(r[0], r[2]); bfmi(r[1], r[3]);
            bf1(r[4], r[6]); bfmi(r[5], r[7]);
            bf1(r[0], r[1]); bf1(r[2], r[3]);
            bf1(r[4], r[5]); bf1(r[6], r[7]);
            int rev8t = (int)(__brev((unsigned)t) >> 24);
            const int rev3[8] = {0, 4, 2, 6, 1, 5, 3, 7};
            __syncthreads();
#pragma unroll
            for (int j = 0; j < 8; j++)
                Z[PADI((rev3[j] << 8) | rev8t)] = r[j];
        }
        __syncthreads();

        // unpack real bins via TW table
        float rsn, rc;
        __sincosf(-3.14159265358979f / 2048.f, &rsn, &rc);
        float tot = 0.f, cen = 0.f, hi = 0.f;
        for (int k = t; k <= NHALF; k += 256) {
            int ik = k & (NHALF - 1);
            int im = (NHALF - k) & (NHALF - 1);
            float2 Zk = Z[PADI(ik)], Zm = Z[PADI(im)];
            float zex = 0.5f * (Zk.x + Zm.x), zey = 0.5f * (Zk.y - Zm.y);
            float zox = 0.5f * (Zk.y + Zm.y), zoy = -0.5f * (Zk.x - Zm.x);
            float2 w = TW[k >> 1];
            float rcc = (k & 1) ? rc : 1.f;
            float rss = (k & 1) ? rsn : 0.f;
            float wx = w.x * rcc - w.y * rss;
            float wy = w.x * rss + w.y * rcc;
            float Xr = zex + wx * zox - wy * zoy;
            float Xi = zey + wx * zoy + wy * zox;
            float p = (Xr * Xr + Xi * Xi) * (1.f / 4096.f);
            tot += p;
            cen += p * ((float)k * (1.f / 2048.f));
            if (k >= 820) hi += p;
        }
        float4 ss = bred_ssss(make_float4(tot, cen, hi, 0.f));
        if (t == 0) {
            float* sp = g_specp + bc * 3;
            sp[0] = ss.x; sp[1] = ss.y; sp[2] = ss.z;
        }
    } else {
        // ======================= svm branch =======================
        int idx = blockIdx.x - BB * CC;
        int b = idx >> 2, quarter = idx & 3;
        int l0 = quarter * 1024 + t * 4;
        const float* xb = x + (size_t)b * CC * LL;

        ull a01 = pk(0.f, 0.f), a23 = a01;
#pragma unroll
        for (int c = 0; c < CC; c++) {
            ulonglong2 v2 = *reinterpret_cast<const ulonglong2*>(xb + (size_t)c * LL + l0);
            fma2(a01, v2.x, v2.x);
            fma2(a23, v2.y, v2.y);
        }
        float q0, q1, q2, q3;
        upk(q0, q1, a01); upk(q2, q3, a23);
        float sv[4] = {sqrtf(q0), sqrtf(q1), sqrtf(q2), sqrtf(q3)};
        *reinterpret_cast<float4*>(g_svm + b * LL + l0) =
            make_float4(sv[0], sv[1], sv[2], sv[3]);

        double s = 0, sq = 0, s2 = 0, sq2 = 0;
        float pre = 0.f, post = 0.f, mx = 0.f, mid = 0.f;
#pragma unroll
        for (int k = 0; k < 4; k++) {
            int l = l0 + k;
            float v = sv[k];
            s += v; sq += (double)v * v;
            if (l >= 2048) { s2 += v; sq2 += (double)v * v; }
            if (l < 1365)      pre += v;
            else if (l < 2730) mid = fmaxf(mid, v);
            else               post += v;
            mx = fmaxf(mx, v);
        }
        s = bsumd(s); sq = bsumd(sq); s2 = bsumd(s2); sq2 = bsumd(sq2);
        float4 pp = bred_ssmm(make_float4(pre, post, mx, mid));
        if (t == 0) {
            double* pd = g_pd + idx * 4;
            pd[0] = s; pd[1] = sq; pd[2] = s2; pd[3] = sq2;
            float* pf = g_pf + idx * 4;
            pf[0] = pp.x; pf[1] = pp.y; pf[2] = pp.z; pf[3] = pp.w;
        }
    }
}

// ---------------- gate: svm finalize + counts + MLPs -> weights ----------------
__global__ void __launch_bounds__(256) k_gate(
        const float* __restrict__ comp_w1, const float* __restrict__ comp_b1,
        const float* __restrict__ comp_w2, const float* __restrict__ comp_b2,
        const float* __restrict__ pn_g, const float* __restrict__ pn_b,
        const float* __restrict__ pn_m, const float* __restrict__ pn_v,
        const float* __restrict__ pe_w1, const float* __restrict__ pe_b1,
        const float* __restrict__ pe_w2, const float* __restrict__ pe_b2,
        const float* __restrict__ pg_w, const float* __restrict__ pg_b,
        const float* __restrict__ temperature) {
    int b = blockIdx.x, t = threadIdx.x;
    __shared__ float xm[CC], h[CC], p1[32], p2[32], pf[12], zz[4];
    __shared__ float sthr[3], sf[4];

    if (t == 0) {
        double s = 0, sq = 0, s2 = 0, sq2 = 0;
        float pre = 0, post = 0, mx = 0, mid = 0;
        for (int q = 0; q < 4; q++) {
            const double* pd = g_pd + (b * 4 + q) * 4;
            s += pd[0]; sq += pd[1]; s2 += pd[2]; sq2 += pd[3];
            const float* pp = g_pf + (b * 4 + q) * 4;
            pre += pp[0]; post += pp[1];
            mx = fmaxf(mx, pp[2]); mid = fmaxf(mid, pp[3]);
        }
        float mean = (float)(s / LL);
        float var1 = (float)((sq - s * s / LL) / (LL - 1));
        float sdev = sqrtf(fmaxf(var1, 0.f)) + 1e-6f;
        sthr[0] = mean + 2.f * sdev;
        sthr[1] = mean + 3.f * sdev;
        sthr[2] = mean - sdev;
        sf[0] = mx; sf[1] = mean;
        double var2 = (sq2 - s2 * s2 / NHALF) / (NHALF - 1);
        float std2 = sqrtf(fmaxf((float)var2, 0.f));
        sf[2] = tanhf(1.f / (std2 + 1e-6f));
        float prem = pre / 1365.f, postm = post / 1366.f;
        float fp = fmaxf(mid - prem, 0.f) + fmaxf(mid - postm, 0.f);
        sf[3] = fp / (fabsf(mid) + 1e-6f);
    }
    __syncthreads();

    float thr = sthr[0], hthr = sthr[1], lthr = sthr[2];
    float c1 = 0.f, c2 = 0.f, c3 = 0.f;
    const float* sr = g_svm + b * LL;
    for (int l = t; l < LL; l += 256) {
        float sv = sr[l];
        if (sv > thr)  c1 += 1.f;
        if (sv > hthr) c2 += 1.f;
        if (sv < lthr) c3 += 1.f;
    }

    float tpv = 0, cnv = 0, hiv = 0, jmv = 0, jrv = 0, zcv = 0;
    if (t < 64) {
        const float* sp = g_specp + (b * 64 + t) * 3;
        tpv = sp[0]; cnv = sp[1]; hiv = sp[2];
        const float* pc = g_percol + (b * 64 + t) * 4;
        xm[t] = pc[0] * (1.f / LL);
        jmv = pc[1]; jrv = pc[2]; zcv = pc[3];
    }
    // merged reductions: 9 -> 3
    float4 rA = bred_ssss(make_float4(c1, c2, c3, tpv));
    float4 rB = bred_ssss(make_float4(cnv, hiv, jmv, jrv));
    float4 rC = bred_ssss(make_float4(zcv, 0.f, 0.f, 0.f));
    float tp = rA.w, cn = rB.x, hh = rB.y;
    float jm = rB.z, jr = rB.w, zc = rC.x;
    c1 = rA.x; c2 = rA.y; c3 = rA.z;

    if (t == 0) {
        float f[12];
        f[0] = sf[0]; f[1] = sf[1]; f[7] = sf[2]; f[11] = sf[3];
        f[2] = jm * (1.f / CC) * 50.f;
        f[3] = jr * (1.f / CC) * 2500.f;
        f[4] = zc * (1.f / CC) * (1.f / LL);
        f[5] = c1 / LL; f[6] = c2 / LL; f[8] = c3 / LL;
        f[9] = cn / (tp + 1e-6f);
        f[10] = hh / (tp + 1e-6f);
        for (int i = 0; i < 12; i++) {
            float v = f[i];
            if (!isfinite(v)) v = 0.f;
            pf[i] = (v - pn_m[i]) * rsqrtf(pn_v[i] + 1e-5f) * pn_g[i] + pn_b[i];
        }
    }
    __syncthreads();

    if (t < 64) {
        float acc = comp_b1[t];
        for (int c = 0; c < CC; c++) acc = fmaf(xm[c], comp_w1[c * CC + t], acc);
        h[t] = fmaxf(acc, 0.f);
        if (t < 32) {
            float q1 = pe_b1[t];
            for (int i = 0; i < 12; i++) q1 = fmaf(pf[i], pe_w1[i * 32 + t], q1);
            p1[t] = fmaxf(q1, 0.f);
        }
    }
    __syncthreads();
    if (t < 32) {
        float q2 = pe_b2[t];
        for (int i = 0; i < 32; i++) q2 = fmaf(p1[i], pe_w2[i * 32 + t], q2);
        p2[t] = fmaxf(q2, 0.f);
    }
    __syncthreads();
    if (t < 4) {
        float lg = comp_b2[t];
        for (int i = 0; i < CC; i++) lg = fmaf(h[i], comp_w2[i * 4 + t], lg);
        float pg = pg_b[t];
        for (int i = 0; i < 32; i++) pg = fmaf(p2[i], pg_w[i * 4 + t], pg);
        float pw = 1.f / (1.f + expf(-pg));
        float temp = fmaxf(temperature[0], 0.1f);
        zz[t] = lg * pw / temp;
    }
    __syncthreads();
    if (t == 0) {
        float m = fmaxf(fmaxf(zz[0], zz[1]), fmaxf(zz[2], zz[3]));
        float e0 = expf(zz[0] - m), e1 = expf(zz[1] - m);
        float e2 = expf(zz[2] - m), e3 = expf(zz[3] - m);
        float si = 1.f / (e0 + e1 + e2 + e3);
        g_weights[b * 4 + 0] = e0 * si;
        g_weights[b * 4 + 1] = e1 * si;
        g_weights[b * 4 + 2] = e2 * si;
        g_weights[b * 4 + 3] = e3 * si;
    }
}

// ---------------- combined 63-tap conv with f32x2 dual-parity window ----------------
#define XS_LEN (LL + 62 + 8)
__global__ void __launch_bounds__(256) k_conv(
        const float* __restrict__ x,
        const float* __restrict__ w7, const float* __restrict__ w15,
        const float* __restrict__ w31, const float* __restrict__ w63,
        const float* __restrict__ bn_g, const float* __restrict__ bn_b,
        const float* __restrict__ bn_m, const float* __restrict__ bn_v) {
    int bc = blockIdx.x;
    int b = bc >> 6, c = bc & 63;
    __shared__ __align__(16) float coef[64];
    __shared__ float sbias;
    __shared__ __align__(16) float xs[XS_LEN];
    int t = threadIdx.x;

    float wk0 = g_weights[b * 4 + 0], wk1 = g_weights[b * 4 + 1];
    float wk2 = g_weights[b * 4 + 2], wk3 = g_weights[b * 4 + 3];
    if (t < 64) {
        float sc0 = bn_g[0 * CC + c] * rsqrtf(bn_v[0 * CC + c] + 1e-5f);
        float sc1 = bn_g[1 * CC + c] * rsqrtf(bn_v[1 * CC + c] + 1e-5f);
        float sc2 = bn_g[2 * CC + c] * rsqrtf(bn_v[2 * CC + c] + 1e-5f);
        float sc3 = bn_g[3 * CC + c] * rsqrtf(bn_v[3 * CC + c] + 1e-5f);
        if (t < 63) {
            int o = t - 31;
            float cf = wk3 * sc3 * w63[c * 63 + t];
            if (o >= -15 && o <= 15) cf += wk2 * sc2 * w31[c * 31 + o + 15];
            if (o >= -7  && o <= 7 ) cf += wk1 * sc1 * w15[c * 15 + o + 7];
            if (o >= -3  && o <= 3 ) cf += wk0 * sc0 * w7 [c * 7  + o + 3];
            coef[t] = cf;
        } else {
            coef[63] = 0.f;
            sbias = wk0 * (bn_b[0 * CC + c] - bn_m[0 * CC + c] * sc0)
                  + wk1 * (bn_b[1 * CC + c] - bn_m[1 * CC + c] * sc1)
                  + wk2 * (bn_b[2 * CC + c] - bn_m[2 * CC + c] * sc2)
                  + wk3 * (bn_b[3 * CC + c] - bn_m[3 * CC + c] * sc3);
        }
    }
    // batched float4 staging
    const float* xr = x + (size_t)bc * LL;
    const float4* xr4 = reinterpret_cast<const float4*>(xr);
    {
        float4 v[4];
#pragma unroll
        for (int i = 0; i < 4; i++) v[i] = xr4[t + 256 * i];
#pragma unroll
        for (int i = 0; i < 4; i++) {
            int j = t + 256 * i;
            xs[31 + 4 * j + 0] = v[i].x;
            xs[31 + 4 * j + 1] = v[i].y;
            xs[31 + 4 * j + 2] = v[i].z;
            xs[31 + 4 * j + 3] = v[i].w;
        }
        if (t < 31) xs[t] = 0.f;
        if (t < XS_LEN - (31 + LL)) xs[31 + LL + t] = 0.f;
    }
    __syncthreads();

    int o0 = t * 16;
    float bias = sbias;
    ull acc2[8];
    ull bias2 = pk(bias, bias);
#pragma unroll
    for (int m = 0; m < 8; m++) acc2[m] = bias2;

    const float4* xs4 = reinterpret_cast<const float4*>(xs + o0);
    const float4* cf4 = reinterpret_cast<const float4*>(coef);

    ull pE[10], pO[9];
    float last;
    {
        float v[20];
#pragma unroll
        for (int q = 0; q < 5; q++) {
            float4 t4 = xs4[q];
            v[4 * q + 0] = t4.x; v[4 * q + 1] = t4.y;
            v[4 * q + 2] = t4.z; v[4 * q + 3] = t4.w;
        }
#pragma unroll
        for (int k = 0; k < 10; k++) pE[k] = pk(v[2 * k], v[2 * k + 1]);
#pragma unroll
        for (int k = 0; k < 9; k++)  pO[k] = pk(v[2 * k + 1], v[2 * k + 2]);
        last = v[19];
    }

#pragma unroll
    for (int g = 0; g < 16; g++) {
        float4 cv = cf4[g];
        ull c0 = pk(cv.x, cv.x), c1 = pk(cv.y, cv.y);
        ull c2 = pk(cv.z, cv.z), c3 = pk(cv.w, cv.w);
#pragma unroll
        for (int m = 0; m < 8; m++) fma2(acc2[m], c0, pE[m]);
#pragma unroll
        for (int m = 0; m < 8; m++) fma2(acc2[m], c1, pO[m]);
#pragma unroll
        for (int m = 0; m < 8; m++) fma2(acc2[m], c2, pE[m + 1]);
#pragma unroll
        for (int m = 0; m < 8; m++) fma2(acc2[m], c3, pO[m + 1]);
        if (g < 15) {
            float4 nv = xs4[5 + g];
#pragma unroll
            for (int m = 0; m < 8; m++) pE[m] = pE[m + 2];
#pragma unroll
            for (int m = 0; m < 7; m++) pO[m] = pO[m + 2];
            pE[8] = pk(nv.x, nv.y); pE[9] = pk(nv.z, nv.w);
            pO[7] = pk(last, nv.x); pO[8] = pk(nv.y, nv.z);
            last = nv.w;
        }
    }

    float outv[16];
#pragma unroll
    for (int m = 0; m < 8; m++) upk(outv[2 * m], outv[2 * m + 1], acc2[m]);

    float ls = 0.f, lsq = 0.f;
    float* mrow = g_mixed + (size_t)bc * LL + o0;
#pragma unroll
    for (int j = 0; j < 16; j += 4) {
        *reinterpret_cast<float4*>(mrow + j) =
            make_float4(outv[j], outv[j + 1], outv[j + 2], outv[j + 3]);
#pragma unroll
        for (int k = 0; k < 4; k++) {
            float v = outv[j + k];
            ls += v; lsq += v * v;
        }
    }
    float4 gred = bred_ssss(make_float4(ls, lsq, 0.f, 0.f));
    if (t == 0) {
        g_gnp[bc * 2 + 0] = gred.x;
        g_gnp[bc * 2 + 1] = gred.y;
    }
}

// ---------------- GN + GELU + 64x64 projection + residual ----------------
#define PROJ_SMEM (64 * 256 * 4 + 64 * 64 * 4)
__global__ void __launch_bounds__(256) k_proj(
        const float* __restrict__ x,
        const float* __restrict__ gn_g, const float* __restrict__ gn_b,
        const float* __restrict__ proj_w, const float* __restrict__ proj_b,
        const float* __restrict__ res_scale, float* __restrict__ out) {
    extern __shared__ __align__(16) float sm[];
    float* As = sm;             // [64][256]
    float* Ws = sm + 64 * 256;  // [c][o] transposed
    int t = threadIdx.x;
    int b = blockIdx.x >> 4;
    int l0 = (blockIdx.x & 15) * 256;

    float sv_ = 0.f, sq_ = 0.f;
    if (t < 64) {
        sv_ = g_gnp[(b * 64 + t) * 2 + 0];
        sq_ = g_gnp[(b * 64 + t) * 2 + 1];
    }
    float4 SQ = bred_ssss(make_float4(sv_, sq_, 0.f, 0.f));
    float n = (float)(CC * LL);
    float mu = SQ.x / n;
    float istd = rsqrtf(SQ.y / n - mu * mu + 1e-5f);

    // stage A = gelu(gn(mixed)) with batched loads
#pragma unroll
    for (int h = 0; h < 2; h++) {
        float4 mv[8];
        float gg[8], gb[8];
#pragma unroll
        for (int i = 0; i < 8; i++) {
            int idx = t + 256 * (h * 8 + i);
            int c = idx >> 6, j = idx & 63;
            mv[i] = *reinterpret_cast<const float4*>(
                g_mixed + (size_t)(b * 64 + c) * LL + l0 + j * 4);
            gg[i] = gn_g[c]; gb[i] = gn_b[c];
        }
#pragma unroll
        for (int i = 0; i < 8; i++) {
            int idx = t + 256 * (h * 8 + i);
            int c = idx >> 6, j = idx & 63;
            float4 av; float v;
            v = (mv[i].x - mu) * istd * gg[i] + gb[i]; av.x = 0.5f * v * (1.f + erff(v * 0.70710678f));
            v = (mv[i].y - mu) * istd * gg[i] + gb[i]; av.y = 0.5f * v * (1.f + erff(v * 0.70710678f));
            v = (mv[i].z - mu) * istd * gg[i] + gb[i]; av.z = 0.5f * v * (1.f + erff(v * 0.70710678f));
            v = (mv[i].w - mu) * istd * gg[i] + gb[i]; av.w = 0.5f * v * (1.f + erff(v * 0.70710678f));
            *reinterpret_cast<float4*>(As + c * 256 + j * 4) = av;
        }
    }
    for (int idx = t; idx < 4096; idx += 256) {
        int c = idx >> 6, o = idx & 63;
        Ws[c * 64 + o] = proj_w[o * CC + c];
    }
    __syncthreads();

    int to = t >> 4, tl = t & 15;
    ull acc2[4][8];
    ull z2 = pk(0.f, 0.f);
#pragma unroll
    for (int i = 0; i < 4; i++)
#pragma unroll
        for (int p = 0; p < 8; p++) acc2[i][p] = z2;

#pragma unroll 4
    for (int c = 0; c < 64; c++) {
        float4 wv = *reinterpret_cast<const float4*>(Ws + c * 64 + to * 4);
        ull w0 = pk(wv.x, wv.x), w1 = pk(wv.y, wv.y);
        ull w2 = pk(wv.z, wv.z), w3 = pk(wv.w, wv.w);
#pragma unroll
        for (int q = 0; q < 4; q++) {
            ulonglong2 aq = *reinterpret_cast<const ulonglong2*>(
                As + c * 256 + q * 64 + tl * 4);
            fma2(acc2[0][2 * q], w0, aq.x); fma2(acc2[0][2 * q + 1], w0, aq.y);
            fma2(acc2[1][2 * q], w1, aq.x); fma2(acc2[1][2 * q + 1], w1, aq.y);
            fma2(acc2[2][2 * q], w2, aq.x); fma2(acc2[2][2 * q + 1], w2, aq.y);
            fma2(acc2[3][2 * q], w3, aq.x); fma2(acc2[3][2 * q + 1], w3, aq.y);
        }
    }

    float rs = res_scale[0];
#pragma unroll
    for (int i = 0; i < 4; i++) {
        int o = to * 4 + i;
        float pb = proj_b[o];
#pragma unroll
        for (int q = 0; q < 4; q++) {
            float f0, f1, f2, f3;
            upk(f0, f1, acc2[i][2 * q]);
            upk(f2, f3, acc2[i][2 * q + 1]);
            size_t base = ((size_t)(b * 64 + o)) * LL + l0 + q * 64 + tl * 4;
            float4 xv = *reinterpret_cast<const float4*>(x + base);
            float4 ov;
            ov.x = xv.x + rs * (f0 + pb);
            ov.y = xv.y + rs * (f1 + pb);
            ov.z = xv.z + rs * (f2 + pb);
            ov.w = xv.w + rs * (f3 + pb);
            *reinterpret_cast<float4*>(out + base) = ov;
        }
    }
}

// ---------------- launch ----------------
extern "C" void kernel_launch(void* const* d_in, const int* in_sizes, int n_in,
                              void* d_out, int out_size) {
    const float* x       = (const float*)d_in[0];
    const float* dw_w7   = (const float*)d_in[1];
    const float* dw_w15  = (const float*)d_in[2];
    const float* dw_w31  = (const float*)d_in[3];
    const float* dw_w63  = (const float*)d_in[4];
    const float* bn_g    = (const float*)d_in[5];
    const float* bn_b    = (const float*)d_in[6];
    const float* bn_m    = (const float*)d_in[7];
    const float* bn_v    = (const float*)d_in[8];
    const float* comp_w1 = (const float*)d_in[9];
    const float* comp_b1 = (const float*)d_in[10];
    const float* comp_w2 = (const float*)d_in[11];
    const float* comp_b2 = (const float*)d_in[12];
    const float* pn_g    = (const float*)d_in[13];
    const float* pn_b    = (const float*)d_in[14];
    const float* pn_m    = (const float*)d_in[15];
    const float* pn_v    = (const float*)d_in[16];
    const float* pe_w1   = (const float*)d_in[17];
    const float* pe_b1   = (const float*)d_in[18];
    const float* pe_w2   = (const float*)d_in[19];
    const float* pe_b2   = (const float*)d_in[20];
    const float* pg_w    = (const float*)d_in[21];
    const float* pg_b    = (const float*)d_in[22];
    const float* temp    = (const float*)d_in[23];
    const float* gn_g    = (const float*)d_in[24];
    const float* gn_b    = (const float*)d_in[25];
    const float* proj_w  = (const float*)d_in[26];
    const float* proj_b  = (const float*)d_in[27];
    const float* rscale  = (const float*)d_in[28];
    float* out = (float*)d_out;

    cudaFuncSetAttribute(k_proj, cudaFuncAttributeMaxDynamicSharedMemorySize, PROJ_SMEM);

    k_fat<<<BB * CC + BB * 4, 256>>>(x);
    k_gate<<<BB, 256>>>(comp_w1, comp_b1, comp_w2, comp_b2,
                        pn_g, pn_b, pn_m, pn_v,
                        pe_w1, pe_b1, pe_w2, pe_b2, pg_w, pg_b, temp);
    k_conv<<<BB * CC, 256>>>(x, dw_w7, dw_w15, dw_w31, dw_w63,
                             bn_g, bn_b, bn_m, bn_v);
    k_proj<<<BB * 16, 256, PROJ_SMEM>>>(x, gn_g, gn_b, proj_w, proj_b, rscale, out);
}